// round 1
// baseline (speedup 1.0000x reference)
#include <cuda_runtime.h>
#include <cuda_bf16.h>
#include <math.h>

// Problem constants
#define BATCH 8
#define SEQ   1024
#define DIM   768
#define HEADS 12
#define HDIM  64
#define M_ROWS (BATCH*SEQ)        // 8192
#define N_QKV  (3*DIM)            // 2304
#define KDIM   DIM                // 768

// Scratch (no allocations allowed -> device globals)
__device__ float g_q[BATCH*HEADS*SEQ*HDIM];   // [B,H,S,Hd]
__device__ float g_k[BATCH*HEADS*SEQ*HDIM];
__device__ float g_v[BATCH*HEADS*SEQ*HDIM];
__device__ float g_o[BATCH*SEQ*DIM];          // [B,S,H*Hd]

// ---------------------------------------------------------------------------
// GEMM 1: qkv = x @ w_qkv + b_qkv, scattered into q/k/v [B,H,S,Hd]
// 128x128 tile, BK=16, 256 threads, 8x8 per thread.
// ---------------------------------------------------------------------------
__global__ __launch_bounds__(256) void sgemm_qkv_kernel(
    const float* __restrict__ A,     // x  [8192][768]
    const float* __restrict__ B,     // w_qkv [768][2304]
    const float* __restrict__ bias)  // [2304]
{
    __shared__ float As[16][132];
    __shared__ float Bs[16][128];

    const int tid = threadIdx.x;
    const int tx = tid & 15, ty = tid >> 4;
    const int rowBase = blockIdx.y * 128;
    const int colBase = blockIdx.x * 128;

    const int ar = tid >> 2;
    const int ac = (tid & 3) << 2;

    float acc[8][8];
#pragma unroll
    for (int i = 0; i < 8; i++)
#pragma unroll
        for (int j = 0; j < 8; j++) acc[i][j] = 0.f;

    for (int k0 = 0; k0 < KDIM; k0 += 16) {
        float4 a0 = *(const float4*)(A + (size_t)(rowBase + ar) * KDIM + k0 + ac);
        float4 a1 = *(const float4*)(A + (size_t)(rowBase + ar + 64) * KDIM + k0 + ac);
        As[ac + 0][ar] = a0.x; As[ac + 1][ar] = a0.y; As[ac + 2][ar] = a0.z; As[ac + 3][ar] = a0.w;
        As[ac + 0][ar + 64] = a1.x; As[ac + 1][ar + 64] = a1.y; As[ac + 2][ar + 64] = a1.z; As[ac + 3][ar + 64] = a1.w;
#pragma unroll
        for (int i = 0; i < 2; i++) {
            int idx = tid + i * 256;
            int br = idx >> 5;
            int bc = (idx & 31) << 2;
            *(float4*)&Bs[br][bc] = *(const float4*)(B + (size_t)(k0 + br) * N_QKV + colBase + bc);
        }
        __syncthreads();
#pragma unroll
        for (int kk = 0; kk < 16; kk++) {
            float4 a0v = *(float4*)&As[kk][ty * 4];
            float4 a1v = *(float4*)&As[kk][64 + ty * 4];
            float4 b0v = *(float4*)&Bs[kk][tx * 4];
            float4 b1v = *(float4*)&Bs[kk][64 + tx * 4];
            float a[8] = {a0v.x, a0v.y, a0v.z, a0v.w, a1v.x, a1v.y, a1v.z, a1v.w};
            float b[8] = {b0v.x, b0v.y, b0v.z, b0v.w, b1v.x, b1v.y, b1v.z, b1v.w};
#pragma unroll
            for (int i = 0; i < 8; i++)
#pragma unroll
                for (int j = 0; j < 8; j++)
                    acc[i][j] = fmaf(a[i], b[j], acc[i][j]);
        }
        __syncthreads();
    }

    // Epilogue: scatter to q/k/v [B,H,S,Hd]
#pragma unroll
    for (int i = 0; i < 8; i++) {
        int m = rowBase + ((i < 4) ? (ty * 4 + i) : (64 + ty * 4 + (i - 4)));
        int b_idx = m >> 10;
        int s_idx = m & 1023;
#pragma unroll
        for (int j = 0; j < 8; j++) {
            int c = colBase + ((j < 4) ? (tx * 4 + j) : (64 + tx * 4 + (j - 4)));
            float val = acc[i][j] + bias[c];
            int which = c / DIM;
            int rem = c - which * DIM;
            int h = rem >> 6;
            int d = rem & 63;
            float* dst = (which == 0) ? g_q : ((which == 1) ? g_k : g_v);
            dst[(((size_t)(b_idx * HEADS + h)) * SEQ + s_idx) * HDIM + d] = val;
        }
    }
}

// ---------------------------------------------------------------------------
// GEMM 2: out = g_o @ w_proj + b_proj
// ---------------------------------------------------------------------------
__global__ __launch_bounds__(256) void sgemm_proj_kernel(
    const float* __restrict__ B,      // w_proj [768][768]
    const float* __restrict__ bias,   // [768]
    float* __restrict__ C)            // [8192][768]
{
    const float* A = g_o;
    __shared__ float As[16][132];
    __shared__ float Bs[16][128];

    const int tid = threadIdx.x;
    const int tx = tid & 15, ty = tid >> 4;
    const int rowBase = blockIdx.y * 128;
    const int colBase = blockIdx.x * 128;

    const int ar = tid >> 2;
    const int ac = (tid & 3) << 2;

    float acc[8][8];
#pragma unroll
    for (int i = 0; i < 8; i++)
#pragma unroll
        for (int j = 0; j < 8; j++) acc[i][j] = 0.f;

    for (int k0 = 0; k0 < KDIM; k0 += 16) {
        float4 a0 = *(const float4*)(A + (size_t)(rowBase + ar) * KDIM + k0 + ac);
        float4 a1 = *(const float4*)(A + (size_t)(rowBase + ar + 64) * KDIM + k0 + ac);
        As[ac + 0][ar] = a0.x; As[ac + 1][ar] = a0.y; As[ac + 2][ar] = a0.z; As[ac + 3][ar] = a0.w;
        As[ac + 0][ar + 64] = a1.x; As[ac + 1][ar + 64] = a1.y; As[ac + 2][ar + 64] = a1.z; As[ac + 3][ar + 64] = a1.w;
#pragma unroll
        for (int i = 0; i < 2; i++) {
            int idx = tid + i * 256;
            int br = idx >> 5;
            int bc = (idx & 31) << 2;
            *(float4*)&Bs[br][bc] = *(const float4*)(B + (size_t)(k0 + br) * DIM + colBase + bc);
        }
        __syncthreads();
#pragma unroll
        for (int kk = 0; kk < 16; kk++) {
            float4 a0v = *(float4*)&As[kk][ty * 4];
            float4 a1v = *(float4*)&As[kk][64 + ty * 4];
            float4 b0v = *(float4*)&Bs[kk][tx * 4];
            float4 b1v = *(float4*)&Bs[kk][64 + tx * 4];
            float a[8] = {a0v.x, a0v.y, a0v.z, a0v.w, a1v.x, a1v.y, a1v.z, a1v.w};
            float b[8] = {b0v.x, b0v.y, b0v.z, b0v.w, b1v.x, b1v.y, b1v.z, b1v.w};
#pragma unroll
            for (int i = 0; i < 8; i++)
#pragma unroll
                for (int j = 0; j < 8; j++)
                    acc[i][j] = fmaf(a[i], b[j], acc[i][j]);
        }
        __syncthreads();
    }

#pragma unroll
    for (int i = 0; i < 8; i++) {
        int m = rowBase + ((i < 4) ? (ty * 4 + i) : (64 + ty * 4 + (i - 4)));
#pragma unroll
        for (int j = 0; j < 8; j++) {
            int c = colBase + ((j < 4) ? (tx * 4 + j) : (64 + tx * 4 + (j - 4)));
            C[(size_t)m * DIM + c] = acc[i][j] + bias[c];
        }
    }
}

// ---------------------------------------------------------------------------
// Flash attention: one block per (bh, q-tile of 64). fp32 online softmax.
// Threads: 256. Thread t: row r = t/4 (0..63), quarter q4 = t%4 (16 cols).
// smem: Qs[64][68], Kst[64][68] (K transposed: [kk][c]), Vs[64][68], Ps[64][68]
// ---------------------------------------------------------------------------
#define AT_STRIDE 68
#define AT_SMEM_FLOATS (4 * 64 * AT_STRIDE)

__global__ __launch_bounds__(256) void attn_kernel(float* __restrict__ dummy_unused)
{
    extern __shared__ float smf[];
    float* Qs  = smf;
    float* Kst = smf + 64 * AT_STRIDE;
    float* Vs  = smf + 2 * 64 * AT_STRIDE;
    float* Ps  = smf + 3 * 64 * AT_STRIDE;

    const int bh = blockIdx.y;          // 0..95
    const int qt = blockIdx.x;          // 0..15
    const int tid = threadIdx.x;
    const int r  = tid >> 2;            // 0..63
    const int q4 = tid & 3;
    const int d0 = q4 * 16;
    const float scale = 0.125f;         // 1/sqrt(64)

    const float* qbase = g_q + (size_t)bh * SEQ * HDIM;
    const float* kbase = g_k + (size_t)bh * SEQ * HDIM;
    const float* vbase = g_v + (size_t)bh * SEQ * HDIM;

    // Load Q tile [64][64]
#pragma unroll
    for (int i = 0; i < 4; i++) {
        int idx = tid + i * 256;
        int row = idx >> 4;
        int c4 = (idx & 15) << 2;
        float4 qv = *(const float4*)(qbase + (size_t)(qt * 64 + row) * HDIM + c4);
        *(float4*)&Qs[row * AT_STRIDE + c4] = qv;
    }

    float m = -1e30f;
    float l = 0.f;
    float acc[16];
#pragma unroll
    for (int j = 0; j < 16; j++) acc[j] = 0.f;

    for (int kt = 0; kt < SEQ / 64; kt++) {
        __syncthreads();   // previous-iter smem reads done before overwrite
        // Load K (transposed into Kst[kk][c]) and V (Vs[k][d])
#pragma unroll
        for (int i = 0; i < 4; i++) {
            int idx = tid + i * 256;
            int c = idx >> 4;
            int k4 = (idx & 15) << 2;
            float4 kv = *(const float4*)(kbase + (size_t)(kt * 64 + c) * HDIM + k4);
            Kst[(k4 + 0) * AT_STRIDE + c] = kv.x;
            Kst[(k4 + 1) * AT_STRIDE + c] = kv.y;
            Kst[(k4 + 2) * AT_STRIDE + c] = kv.z;
            Kst[(k4 + 3) * AT_STRIDE + c] = kv.w;
            float4 vv = *(const float4*)(vbase + (size_t)(kt * 64 + c) * HDIM + k4);
            *(float4*)&Vs[c * AT_STRIDE + k4] = vv;
        }
        __syncthreads();

        // S[r][d0..d0+15] = Q[r] . K[c]
        float s[16];
#pragma unroll
        for (int j = 0; j < 16; j++) s[j] = 0.f;
#pragma unroll 8
        for (int kk = 0; kk < 64; kk++) {
            float qv = Qs[r * AT_STRIDE + kk];
            float4 k0v = *(float4*)&Kst[kk * AT_STRIDE + d0];
            float4 k1v = *(float4*)&Kst[kk * AT_STRIDE + d0 + 4];
            float4 k2v = *(float4*)&Kst[kk * AT_STRIDE + d0 + 8];
            float4 k3v = *(float4*)&Kst[kk * AT_STRIDE + d0 + 12];
            s[0]  = fmaf(qv, k0v.x, s[0]);  s[1]  = fmaf(qv, k0v.y, s[1]);
            s[2]  = fmaf(qv, k0v.z, s[2]);  s[3]  = fmaf(qv, k0v.w, s[3]);
            s[4]  = fmaf(qv, k1v.x, s[4]);  s[5]  = fmaf(qv, k1v.y, s[5]);
            s[6]  = fmaf(qv, k1v.z, s[6]);  s[7]  = fmaf(qv, k1v.w, s[7]);
            s[8]  = fmaf(qv, k2v.x, s[8]);  s[9]  = fmaf(qv, k2v.y, s[9]);
            s[10] = fmaf(qv, k2v.z, s[10]); s[11] = fmaf(qv, k2v.w, s[11]);
            s[12] = fmaf(qv, k3v.x, s[12]); s[13] = fmaf(qv, k3v.y, s[13]);
            s[14] = fmaf(qv, k3v.z, s[14]); s[15] = fmaf(qv, k3v.w, s[15]);
        }

        // online softmax (row split across 4 lanes of the same warp group)
        float lm = -1e30f;
#pragma unroll
        for (int j = 0; j < 16; j++) { s[j] *= scale; lm = fmaxf(lm, s[j]); }
        lm = fmaxf(lm, __shfl_xor_sync(0xffffffffu, lm, 1));
        lm = fmaxf(lm, __shfl_xor_sync(0xffffffffu, lm, 2));
        float mnew = fmaxf(m, lm);
        float corr = __expf(m - mnew);
        float p[16];
        float ls = 0.f;
#pragma unroll
        for (int j = 0; j < 16; j++) { p[j] = __expf(s[j] - mnew); ls += p[j]; }
        ls += __shfl_xor_sync(0xffffffffu, ls, 1);
        ls += __shfl_xor_sync(0xffffffffu, ls, 2);
        l = l * corr + ls;
        m = mnew;
#pragma unroll
        for (int j = 0; j < 16; j++) acc[j] *= corr;
#pragma unroll
        for (int j = 0; j < 16; j++) Ps[r * AT_STRIDE + d0 + j] = p[j];
        __syncwarp();   // row's P written by 4 lanes of the same warp

        // O[r][d0..] += P[r][:] @ V[:][d0..]
#pragma unroll 8
        for (int kk = 0; kk < 64; kk++) {
            float pv = Ps[r * AT_STRIDE + kk];
            float4 v0 = *(float4*)&Vs[kk * AT_STRIDE + d0];
            float4 v1 = *(float4*)&Vs[kk * AT_STRIDE + d0 + 4];
            float4 v2 = *(float4*)&Vs[kk * AT_STRIDE + d0 + 8];
            float4 v3 = *(float4*)&Vs[kk * AT_STRIDE + d0 + 12];
            acc[0]  = fmaf(pv, v0.x, acc[0]);  acc[1]  = fmaf(pv, v0.y, acc[1]);
            acc[2]  = fmaf(pv, v0.z, acc[2]);  acc[3]  = fmaf(pv, v0.w, acc[3]);
            acc[4]  = fmaf(pv, v1.x, acc[4]);  acc[5]  = fmaf(pv, v1.y, acc[5]);
            acc[6]  = fmaf(pv, v1.z, acc[6]);  acc[7]  = fmaf(pv, v1.w, acc[7]);
            acc[8]  = fmaf(pv, v2.x, acc[8]);  acc[9]  = fmaf(pv, v2.y, acc[9]);
            acc[10] = fmaf(pv, v2.z, acc[10]); acc[11] = fmaf(pv, v2.w, acc[11]);
            acc[12] = fmaf(pv, v3.x, acc[12]); acc[13] = fmaf(pv, v3.y, acc[13]);
            acc[14] = fmaf(pv, v3.z, acc[14]); acc[15] = fmaf(pv, v3.w, acc[15]);
        }
    }

    float inv = 1.f / l;
    int b = bh / HEADS, h = bh - (bh / HEADS) * HEADS;
    int srow = qt * 64 + r;
    float* outp = g_o + ((size_t)(b * SEQ + srow)) * DIM + h * HDIM + d0;
#pragma unroll
    for (int j = 0; j < 16; j++) outp[j] = acc[j] * inv;
}

// ---------------------------------------------------------------------------
extern "C" void kernel_launch(void* const* d_in, const int* in_sizes, int n_in,
                              void* d_out, int out_size) {
    const float* x      = (const float*)d_in[0];
    const float* w_qkv  = (const float*)d_in[1];
    const float* b_qkv  = (const float*)d_in[2];
    const float* w_proj = (const float*)d_in[3];
    const float* b_proj = (const float*)d_in[4];
    float* out = (float*)d_out;

    // allow 68KB dynamic smem for the attention kernel (idempotent)
    static bool attr_set = false;
    (void)attr_set;
    cudaFuncSetAttribute(attn_kernel, cudaFuncAttributeMaxDynamicSharedMemorySize,
                         AT_SMEM_FLOATS * (int)sizeof(float));

    // GEMM1: [8192 x 2304] = x @ w_qkv
    {
        dim3 grid(N_QKV / 128, M_ROWS / 128);
        sgemm_qkv_kernel<<<grid, 256>>>(x, w_qkv, b_qkv);
    }
    // Attention: 96 (b*h) x 16 q-tiles
    {
        dim3 grid(SEQ / 64, BATCH * HEADS);
        attn_kernel<<<grid, 256, AT_SMEM_FLOATS * (int)sizeof(float)>>>(nullptr);
    }
    // GEMM2: [8192 x 768] = g_o @ w_proj
    {
        dim3 grid(DIM / 128, M_ROWS / 128);
        sgemm_proj_kernel<<<grid, 256>>>(w_proj, b_proj, out);
    }
}

// round 2
// speedup vs baseline: 5.7262x; 5.7262x over previous
#include <cuda_runtime.h>
#include <cuda_bf16.h>
#include <math.h>
#include <stdint.h>

#define BATCH 8
#define SEQ   1024
#define DIM   768
#define HEADS 12
#define HDIM  64
#define M_ROWS (BATCH*SEQ)        // 8192
#define N_QKV  (3*DIM)            // 2304

#define DINLINE __device__ __forceinline__

// ---------------- scratch: pre-split bf16 hi/lo planes ----------------
#define QKV_ELEMS (BATCH*HEADS*SEQ*HDIM)   // 6291456
__device__ __nv_bfloat16 g_q_hi[QKV_ELEMS], g_q_lo[QKV_ELEMS];
__device__ __nv_bfloat16 g_k_hi[QKV_ELEMS], g_k_lo[QKV_ELEMS];
__device__ __nv_bfloat16 g_v_hi[QKV_ELEMS], g_v_lo[QKV_ELEMS];
__device__ __nv_bfloat16 g_o_hi[M_ROWS*DIM], g_o_lo[M_ROWS*DIM];

// ---------------- PTX helpers ----------------
DINLINE uint32_t smem_u32(const void* p) { return (uint32_t)__cvta_generic_to_shared(p); }

DINLINE void ldsm4(uint32_t r[4], uint32_t a) {
    asm volatile("ldmatrix.sync.aligned.m8n8.x4.shared.b16 {%0,%1,%2,%3},[%4];"
                 : "=r"(r[0]), "=r"(r[1]), "=r"(r[2]), "=r"(r[3]) : "r"(a));
}
DINLINE void ldsm4t(uint32_t r[4], uint32_t a) {
    asm volatile("ldmatrix.sync.aligned.m8n8.x4.trans.shared.b16 {%0,%1,%2,%3},[%4];"
                 : "=r"(r[0]), "=r"(r[1]), "=r"(r[2]), "=r"(r[3]) : "r"(a));
}
DINLINE void mma16816(float c[4], const uint32_t a[4], const uint32_t b[2]) {
    asm volatile("mma.sync.aligned.m16n8k16.row.col.f32.bf16.bf16.f32 "
                 "{%0,%1,%2,%3},{%4,%5,%6,%7},{%8,%9},{%0,%1,%2,%3};"
                 : "+f"(c[0]), "+f"(c[1]), "+f"(c[2]), "+f"(c[3])
                 : "r"(a[0]), "r"(a[1]), "r"(a[2]), "r"(a[3]), "r"(b[0]), "r"(b[1]));
}

// split fp32 pair into packed bf16 hi/lo (x -> low half, y -> high half)
DINLINE void split2(float x, float y, uint32_t &hi, uint32_t &lo) {
    __nv_bfloat16 hx = __float2bfloat16(x);
    __nv_bfloat16 hy = __float2bfloat16(y);
    float rx = x - __bfloat162float(hx);
    float ry = y - __bfloat162float(hy);
    __nv_bfloat162 h2; h2.x = hx; h2.y = hy;
    __nv_bfloat162 l2; l2.x = __float2bfloat16(rx); l2.y = __float2bfloat16(ry);
    hi = *reinterpret_cast<uint32_t*>(&h2);
    lo = *reinterpret_cast<uint32_t*>(&l2);
}
DINLINE void store_split4(__nv_bfloat16* hi, __nv_bfloat16* lo, float4 v) {
    uint32_t h0, l0, h1, l1;
    split2(v.x, v.y, h0, l0);
    split2(v.z, v.w, h1, l1);
    ((uint32_t*)hi)[0] = h0; ((uint32_t*)hi)[1] = h1;
    ((uint32_t*)lo)[0] = l0; ((uint32_t*)lo)[1] = l1;
}

#define PA 40     // A smem pitch (bf16 elems): 80B, conflict-free
#define PB 136    // B smem pitch: 272B, conflict-free

// ===========================================================================
// GEMM 1: qkv = x @ w_qkv + b_qkv  (fp32 in, bf16x3 mma, split-epilogue out)
// block 128x128, BK=32, 256 thr, warp tile 64x32
// ===========================================================================
__global__ __launch_bounds__(256) void qkv_kernel(
    const float* __restrict__ A, const float* __restrict__ B,
    const float* __restrict__ bias)
{
    __shared__ __nv_bfloat16 As_hi[128*PA], As_lo[128*PA];
    __shared__ __nv_bfloat16 Bs_hi[32*PB],  Bs_lo[32*PB];

    const int tid = threadIdx.x, lane = tid & 31, warp = tid >> 5;
    const int warp_m = warp >> 2, warp_n = warp & 3;
    const int rowBase = blockIdx.y * 128, colBase = blockIdx.x * 128;
    const int lrA = tid >> 1, lcA = (tid & 1) * 16;
    const int lrB = tid >> 3, lcB = (tid & 7) * 16;

    const int a_row = warp_m * 64 + (lane & 7) + 8 * ((lane >> 3) & 1);
    const int a_col = 8 * (lane >> 4);
    const int b_krow = (lane & 7) + 8 * ((lane >> 3) & 1);
    const int b_ncol = warp_n * 32 + 8 * (lane >> 4);

    float acc[4][4][4];
#pragma unroll
    for (int i = 0; i < 4; i++)
#pragma unroll
        for (int j = 0; j < 4; j++)
#pragma unroll
            for (int e = 0; e < 4; e++) acc[i][j][e] = 0.f;

    float4 pa[4], pb[4];
#pragma unroll
    for (int i = 0; i < 4; i++) {
        pa[i] = *(const float4*)(A + (size_t)(rowBase + lrA) * DIM + lcA + i * 4);
        pb[i] = *(const float4*)(B + (size_t)lrB * N_QKV + colBase + lcB + i * 4);
    }

    for (int k0 = 0; k0 < DIM; k0 += 32) {
        __syncthreads();
#pragma unroll
        for (int i = 0; i < 4; i++) {
            store_split4(&As_hi[lrA*PA + lcA + i*4], &As_lo[lrA*PA + lcA + i*4], pa[i]);
            store_split4(&Bs_hi[lrB*PB + lcB + i*4], &Bs_lo[lrB*PB + lcB + i*4], pb[i]);
        }
        __syncthreads();
        if (k0 + 32 < DIM) {
#pragma unroll
            for (int i = 0; i < 4; i++) {
                pa[i] = *(const float4*)(A + (size_t)(rowBase + lrA) * DIM + (k0 + 32) + lcA + i * 4);
                pb[i] = *(const float4*)(B + (size_t)(k0 + 32 + lrB) * N_QKV + colBase + lcB + i * 4);
            }
        }
#pragma unroll
        for (int ks = 0; ks < 32; ks += 16) {
            uint32_t ah[4][4], al[4][4];
#pragma unroll
            for (int ma = 0; ma < 4; ma++) {
                int off = (a_row + ma * 16) * PA + ks + a_col;
                ldsm4(ah[ma], smem_u32(&As_hi[off]));
                ldsm4(al[ma], smem_u32(&As_lo[off]));
            }
            uint32_t bh[2][4], bl[2][4];
#pragma unroll
            for (int nb = 0; nb < 2; nb++) {
                int off = (ks + b_krow) * PB + b_ncol + nb * 16;
                ldsm4t(bh[nb], smem_u32(&Bs_hi[off]));
                ldsm4t(bl[nb], smem_u32(&Bs_lo[off]));
            }
#pragma unroll
            for (int ma = 0; ma < 4; ma++)
#pragma unroll
                for (int na = 0; na < 4; na++)
                    mma16816(acc[ma][na], ah[ma], &bh[na >> 1][(na & 1) * 2]);
#pragma unroll
            for (int ma = 0; ma < 4; ma++)
#pragma unroll
                for (int na = 0; na < 4; na++)
                    mma16816(acc[ma][na], ah[ma], &bl[na >> 1][(na & 1) * 2]);
#pragma unroll
            for (int ma = 0; ma < 4; ma++)
#pragma unroll
                for (int na = 0; na < 4; na++)
                    mma16816(acc[ma][na], al[ma], &bh[na >> 1][(na & 1) * 2]);
        }
    }

    // epilogue: +bias, split to bf16 hi/lo, scatter into q/k/v [B,H,S,Hd]
    const int g = lane >> 2, t = lane & 3;
#pragma unroll
    for (int ma = 0; ma < 4; ma++) {
        int r0 = rowBase + warp_m * 64 + ma * 16 + g;
#pragma unroll
        for (int half = 0; half < 2; half++) {
            int row = r0 + half * 8;
            int bidx = row >> 10, srow = row & 1023;
#pragma unroll
            for (int na = 0; na < 4; na++) {
                int col = colBase + warp_n * 32 + na * 8 + 2 * t;
                float v0 = acc[ma][na][half * 2 + 0] + bias[col];
                float v1 = acc[ma][na][half * 2 + 1] + bias[col + 1];
                int which = col / DIM;
                int rem = col - which * DIM;
                int h = rem >> 6, d = rem & 63;
                size_t idx = (((size_t)(bidx * HEADS + h)) * SEQ + srow) * HDIM + d;
                __nv_bfloat16 *dh, *dl;
                if (which == 0)      { dh = g_q_hi; dl = g_q_lo; }
                else if (which == 1) { dh = g_k_hi; dl = g_k_lo; }
                else                 { dh = g_v_hi; dl = g_v_lo; }
                uint32_t hi, lo;
                split2(v0, v1, hi, lo);
                *(uint32_t*)(dh + idx) = hi;
                *(uint32_t*)(dl + idx) = lo;
            }
        }
    }
}

// ===========================================================================
// GEMM 2: out = O @ w_proj + b_proj  (A already bf16 hi/lo, B fp32)
// ===========================================================================
__global__ __launch_bounds__(256) void proj_kernel(
    const float* __restrict__ B, const float* __restrict__ bias,
    float* __restrict__ C)
{
    __shared__ __nv_bfloat16 As_hi[128*PA], As_lo[128*PA];
    __shared__ __nv_bfloat16 Bs_hi[32*PB],  Bs_lo[32*PB];

    const int tid = threadIdx.x, lane = tid & 31, warp = tid >> 5;
    const int warp_m = warp >> 2, warp_n = warp & 3;
    const int rowBase = blockIdx.y * 128, colBase = blockIdx.x * 128;
    const int lrB = tid >> 3, lcB = (tid & 7) * 16;

    const int a_row = warp_m * 64 + (lane & 7) + 8 * ((lane >> 3) & 1);
    const int a_col = 8 * (lane >> 4);
    const int b_krow = (lane & 7) + 8 * ((lane >> 3) & 1);
    const int b_ncol = warp_n * 32 + 8 * (lane >> 4);

    float acc[4][4][4];
#pragma unroll
    for (int i = 0; i < 4; i++)
#pragma unroll
        for (int j = 0; j < 4; j++)
#pragma unroll
            for (int e = 0; e < 4; e++) acc[i][j][e] = 0.f;

    uint4 pah[2], pal[2];
    float4 pb[4];
#pragma unroll
    for (int i = 0; i < 2; i++) {
        int c = tid + i * 256;
        int row = c >> 2, c8 = (c & 3) * 8;
        size_t src = (size_t)(rowBase + row) * DIM + c8;
        pah[i] = *(const uint4*)(g_o_hi + src);
        pal[i] = *(const uint4*)(g_o_lo + src);
    }
#pragma unroll
    for (int i = 0; i < 4; i++)
        pb[i] = *(const float4*)(B + (size_t)lrB * DIM + colBase + lcB + i * 4);

    for (int k0 = 0; k0 < DIM; k0 += 32) {
        __syncthreads();
#pragma unroll
        for (int i = 0; i < 2; i++) {
            int c = tid + i * 256;
            int row = c >> 2, c8 = (c & 3) * 8;
            *(uint4*)(&As_hi[row * PA + c8]) = pah[i];
            *(uint4*)(&As_lo[row * PA + c8]) = pal[i];
        }
#pragma unroll
        for (int i = 0; i < 4; i++)
            store_split4(&Bs_hi[lrB*PB + lcB + i*4], &Bs_lo[lrB*PB + lcB + i*4], pb[i]);
        __syncthreads();
        if (k0 + 32 < DIM) {
#pragma unroll
            for (int i = 0; i < 2; i++) {
                int c = tid + i * 256;
                int row = c >> 2, c8 = (c & 3) * 8;
                size_t src = (size_t)(rowBase + row) * DIM + (k0 + 32) + c8;
                pah[i] = *(const uint4*)(g_o_hi + src);
                pal[i] = *(const uint4*)(g_o_lo + src);
            }
#pragma unroll
            for (int i = 0; i < 4; i++)
                pb[i] = *(const float4*)(B + (size_t)(k0 + 32 + lrB) * DIM + colBase + lcB + i * 4);
        }
#pragma unroll
        for (int ks = 0; ks < 32; ks += 16) {
            uint32_t ah[4][4], al[4][4];
#pragma unroll
            for (int ma = 0; ma < 4; ma++) {
                int off = (a_row + ma * 16) * PA + ks + a_col;
                ldsm4(ah[ma], smem_u32(&As_hi[off]));
                ldsm4(al[ma], smem_u32(&As_lo[off]));
            }
            uint32_t bh[2][4], bl[2][4];
#pragma unroll
            for (int nb = 0; nb < 2; nb++) {
                int off = (ks + b_krow) * PB + b_ncol + nb * 16;
                ldsm4t(bh[nb], smem_u32(&Bs_hi[off]));
                ldsm4t(bl[nb], smem_u32(&Bs_lo[off]));
            }
#pragma unroll
            for (int ma = 0; ma < 4; ma++)
#pragma unroll
                for (int na = 0; na < 4; na++)
                    mma16816(acc[ma][na], ah[ma], &bh[na >> 1][(na & 1) * 2]);
#pragma unroll
            for (int ma = 0; ma < 4; ma++)
#pragma unroll
                for (int na = 0; na < 4; na++)
                    mma16816(acc[ma][na], ah[ma], &bl[na >> 1][(na & 1) * 2]);
#pragma unroll
            for (int ma = 0; ma < 4; ma++)
#pragma unroll
                for (int na = 0; na < 4; na++)
                    mma16816(acc[ma][na], al[ma], &bh[na >> 1][(na & 1) * 2]);
        }
    }

    const int g = lane >> 2, t = lane & 3;
#pragma unroll
    for (int ma = 0; ma < 4; ma++) {
        int r0 = rowBase + warp_m * 64 + ma * 16 + g;
#pragma unroll
        for (int half = 0; half < 2; half++) {
            int row = r0 + half * 8;
#pragma unroll
            for (int na = 0; na < 4; na++) {
                int col = colBase + warp_n * 32 + na * 8 + 2 * t;
                float2 o;
                o.x = acc[ma][na][half * 2 + 0] + bias[col];
                o.y = acc[ma][na][half * 2 + 1] + bias[col + 1];
                *(float2*)(&C[(size_t)row * DIM + col]) = o;
            }
        }
    }
}

// ===========================================================================
// Flash attention, tensor cores, bf16x3. Block: 8 warps, Br=128, Bc=64.
// ===========================================================================
#define QPITCH 72
#define Q_PLANE (128*QPITCH)
#define KV_PLANE (64*QPITCH)
#define AT_SMEM_BYTES ((2*Q_PLANE + 4*KV_PLANE) * 2)

__global__ __launch_bounds__(256) void attn_kernel()
{
    extern __shared__ __nv_bfloat16 smb[];
    __nv_bfloat16* Qs_hi = smb;
    __nv_bfloat16* Qs_lo = Qs_hi + Q_PLANE;
    __nv_bfloat16* Ks_hi = Qs_lo + Q_PLANE;
    __nv_bfloat16* Ks_lo = Ks_hi + KV_PLANE;
    __nv_bfloat16* Vs_hi = Ks_lo + KV_PLANE;
    __nv_bfloat16* Vs_lo = Vs_hi + KV_PLANE;

    const int tid = threadIdx.x, lane = tid & 31, warp = tid >> 5;
    const int bh = blockIdx.y, qt = blockIdx.x;
    const int g = lane >> 2, t = lane & 3;
    const float scale = 0.125f;

    const size_t base = (size_t)bh * SEQ * HDIM;
    const __nv_bfloat16* qh = g_q_hi + base; const __nv_bfloat16* ql = g_q_lo + base;
    const __nv_bfloat16* kh = g_k_hi + base; const __nv_bfloat16* kl = g_k_lo + base;
    const __nv_bfloat16* vh = g_v_hi + base; const __nv_bfloat16* vl = g_v_lo + base;

    // load Q tile (128x64) hi/lo into smem
#pragma unroll
    for (int i = 0; i < 4; i++) {
        int c = tid + i * 256;
        int row = c >> 3, c8 = (c & 7) * 8;
        size_t src = (size_t)(qt * 128 + row) * HDIM + c8;
        *(uint4*)(&Qs_hi[row * QPITCH + c8]) = *(const uint4*)(qh + src);
        *(uint4*)(&Qs_lo[row * QPITCH + c8]) = *(const uint4*)(ql + src);
    }

    // preload KV tile 0 into regs
    const int kvr = tid >> 3, kvc = (tid & 7) * 8;
    uint4 pre[8];
    {
        size_t s0 = (size_t)kvr * HDIM + kvc, s1 = s0 + (size_t)32 * HDIM;
        pre[0] = *(const uint4*)(kh + s0); pre[1] = *(const uint4*)(kh + s1);
        pre[2] = *(const uint4*)(kl + s0); pre[3] = *(const uint4*)(kl + s1);
        pre[4] = *(const uint4*)(vh + s0); pre[5] = *(const uint4*)(vh + s1);
        pre[6] = *(const uint4*)(vl + s0); pre[7] = *(const uint4*)(vl + s1);
    }
    __syncthreads();

    // Q fragments (A operand), resident in regs
    const int a_row = warp * 16 + (lane & 7) + 8 * ((lane >> 3) & 1);
    const int a_col = 8 * (lane >> 4);
    uint32_t qfh[4][4], qfl[4][4];
#pragma unroll
    for (int ka = 0; ka < 4; ka++) {
        int off = a_row * QPITCH + ka * 16 + a_col;
        ldsm4(qfh[ka], smem_u32(&Qs_hi[off]));
        ldsm4(qfl[ka], smem_u32(&Qs_lo[off]));
    }

    // lane addressing for K (no-trans) and V (trans)
    const int k_row = (lane & 7) + 8 * (lane >> 4);
    const int k_col = 8 * ((lane >> 3) & 1);
    const int v_row = (lane & 7) + 8 * ((lane >> 3) & 1);
    const int v_col = 8 * (lane >> 4);

    float m0 = -1e30f, m1 = -1e30f, l0 = 0.f, l1 = 0.f;
    float o[8][4];
#pragma unroll
    for (int j = 0; j < 8; j++)
#pragma unroll
        for (int e = 0; e < 4; e++) o[j][e] = 0.f;

    for (int kt = 0; kt < SEQ / 64; kt++) {
        __syncthreads();
        *(uint4*)(&Ks_hi[kvr * QPITCH + kvc]) = pre[0];
        *(uint4*)(&Ks_hi[(kvr + 32) * QPITCH + kvc]) = pre[1];
        *(uint4*)(&Ks_lo[kvr * QPITCH + kvc]) = pre[2];
        *(uint4*)(&Ks_lo[(kvr + 32) * QPITCH + kvc]) = pre[3];
        *(uint4*)(&Vs_hi[kvr * QPITCH + kvc]) = pre[4];
        *(uint4*)(&Vs_hi[(kvr + 32) * QPITCH + kvc]) = pre[5];
        *(uint4*)(&Vs_lo[kvr * QPITCH + kvc]) = pre[6];
        *(uint4*)(&Vs_lo[(kvr + 32) * QPITCH + kvc]) = pre[7];
        __syncthreads();
        if (kt + 1 < SEQ / 64) {
            size_t s0 = (size_t)((kt + 1) * 64 + kvr) * HDIM + kvc;
            size_t s1 = s0 + (size_t)32 * HDIM;
            pre[0] = *(const uint4*)(kh + s0); pre[1] = *(const uint4*)(kh + s1);
            pre[2] = *(const uint4*)(kl + s0); pre[3] = *(const uint4*)(kl + s1);
            pre[4] = *(const uint4*)(vh + s0); pre[5] = *(const uint4*)(vh + s1);
            pre[6] = *(const uint4*)(vl + s0); pre[7] = *(const uint4*)(vl + s1);
        }

        // ---- S = Q K^T (bf16x3) ----
        float s[8][4];
#pragma unroll
        for (int j = 0; j < 8; j++)
#pragma unroll
            for (int e = 0; e < 4; e++) s[j][e] = 0.f;

#pragma unroll
        for (int nb = 0; nb < 4; nb++) {
#pragma unroll
            for (int ka = 0; ka < 4; ka++) {
                int off = (nb * 16 + k_row) * QPITCH + ka * 16 + k_col;
                uint32_t kfh[4], kfl[4];
                ldsm4(kfh, smem_u32(&Ks_hi[off]));
                ldsm4(kfl, smem_u32(&Ks_lo[off]));
                mma16816(s[2*nb],   qfh[ka], &kfh[0]);
                mma16816(s[2*nb+1], qfh[ka], &kfh[2]);
                mma16816(s[2*nb],   qfh[ka], &kfl[0]);
                mma16816(s[2*nb+1], qfh[ka], &kfl[2]);
                mma16816(s[2*nb],   qfl[ka], &kfh[0]);
                mma16816(s[2*nb+1], qfl[ka], &kfh[2]);
            }
        }

        // ---- online softmax ----
        float mx0 = -1e30f, mx1 = -1e30f;
#pragma unroll
        for (int j = 0; j < 8; j++) {
            s[j][0] *= scale; s[j][1] *= scale; s[j][2] *= scale; s[j][3] *= scale;
            mx0 = fmaxf(mx0, fmaxf(s[j][0], s[j][1]));
            mx1 = fmaxf(mx1, fmaxf(s[j][2], s[j][3]));
        }
        mx0 = fmaxf(mx0, __shfl_xor_sync(0xffffffffu, mx0, 1));
        mx0 = fmaxf(mx0, __shfl_xor_sync(0xffffffffu, mx0, 2));
        mx1 = fmaxf(mx1, __shfl_xor_sync(0xffffffffu, mx1, 1));
        mx1 = fmaxf(mx1, __shfl_xor_sync(0xffffffffu, mx1, 2));
        float mn0 = fmaxf(m0, mx0), mn1 = fmaxf(m1, mx1);
        float c0 = __expf(m0 - mn0), c1 = __expf(m1 - mn1);
        float p[8][4];
        float ls0 = 0.f, ls1 = 0.f;
#pragma unroll
        for (int j = 0; j < 8; j++) {
            p[j][0] = __expf(s[j][0] - mn0); p[j][1] = __expf(s[j][1] - mn0);
            p[j][2] = __expf(s[j][2] - mn1); p[j][3] = __expf(s[j][3] - mn1);
            ls0 += p[j][0] + p[j][1];
            ls1 += p[j][2] + p[j][3];
        }
        ls0 += __shfl_xor_sync(0xffffffffu, ls0, 1);
        ls0 += __shfl_xor_sync(0xffffffffu, ls0, 2);
        ls1 += __shfl_xor_sync(0xffffffffu, ls1, 1);
        ls1 += __shfl_xor_sync(0xffffffffu, ls1, 2);
        l0 = l0 * c0 + ls0; m0 = mn0;
        l1 = l1 * c1 + ls1; m1 = mn1;
#pragma unroll
        for (int j = 0; j < 8; j++) {
            o[j][0] *= c0; o[j][1] *= c0; o[j][2] *= c1; o[j][3] *= c1;
        }

        // ---- P fragments (A operand for PV) ----
        uint32_t pfh[4][4], pfl[4][4];
#pragma unroll
        for (int ka = 0; ka < 4; ka++) {
            split2(p[2*ka][0],   p[2*ka][1],   pfh[ka][0], pfl[ka][0]);
            split2(p[2*ka][2],   p[2*ka][3],   pfh[ka][1], pfl[ka][1]);
            split2(p[2*ka+1][0], p[2*ka+1][1], pfh[ka][2], pfl[ka][2]);
            split2(p[2*ka+1][2], p[2*ka+1][3], pfh[ka][3], pfl[ka][3]);
        }

        // ---- O += P V (bf16x3) ----
#pragma unroll
        for (int nb = 0; nb < 4; nb++) {
#pragma unroll
            for (int ka = 0; ka < 4; ka++) {
                int off = (ka * 16 + v_row) * QPITCH + nb * 16 + v_col;
                uint32_t vfh[4], vfl[4];
                ldsm4t(vfh, smem_u32(&Vs_hi[off]));
                ldsm4t(vfl, smem_u32(&Vs_lo[off]));
                mma16816(o[2*nb],   pfh[ka], &vfh[0]);
                mma16816(o[2*nb+1], pfh[ka], &vfh[2]);
                mma16816(o[2*nb],   pfh[ka], &vfl[0]);
                mma16816(o[2*nb+1], pfh[ka], &vfl[2]);
                mma16816(o[2*nb],   pfl[ka], &vfh[0]);
                mma16816(o[2*nb+1], pfl[ka], &vfh[2]);
            }
        }
    }

    // ---- normalize + write O as hi/lo bf16 into [B,S,D] planes ----
    float i0 = 1.f / l0, i1 = 1.f / l1;
    int b = bh / HEADS, h = bh - (bh / HEADS) * HEADS;
    int srow0 = qt * 128 + warp * 16 + g;
    int srow1 = srow0 + 8;
#pragma unroll
    for (int j = 0; j < 8; j++) {
        int col = h * HDIM + j * 8 + 2 * t;
        size_t i0x = ((size_t)(b * SEQ) + srow0) * DIM + col;
        size_t i1x = ((size_t)(b * SEQ) + srow1) * DIM + col;
        uint32_t hi, lo;
        split2(o[j][0] * i0, o[j][1] * i0, hi, lo);
        *(uint32_t*)(g_o_hi + i0x) = hi;
        *(uint32_t*)(g_o_lo + i0x) = lo;
        split2(o[j][2] * i1, o[j][3] * i1, hi, lo);
        *(uint32_t*)(g_o_hi + i1x) = hi;
        *(uint32_t*)(g_o_lo + i1x) = lo;
    }
}

// ===========================================================================
extern "C" void kernel_launch(void* const* d_in, const int* in_sizes, int n_in,
                              void* d_out, int out_size) {
    const float* x      = (const float*)d_in[0];
    const float* w_qkv  = (const float*)d_in[1];
    const float* b_qkv  = (const float*)d_in[2];
    const float* w_proj = (const float*)d_in[3];
    const float* b_proj = (const float*)d_in[4];
    float* out = (float*)d_out;

    cudaFuncSetAttribute(attn_kernel, cudaFuncAttributeMaxDynamicSharedMemorySize,
                         AT_SMEM_BYTES);

    {
        dim3 grid(N_QKV / 128, M_ROWS / 128);
        qkv_kernel<<<grid, 256>>>(x, w_qkv, b_qkv);
    }
    {
        dim3 grid(SEQ / 128, BATCH * HEADS);
        attn_kernel<<<grid, 256, AT_SMEM_BYTES>>>();
    }
    {
        dim3 grid(DIM / 128, M_ROWS / 128);
        proj_kernel<<<grid, 256>>>(w_proj, b_proj, out);
    }
}

// round 6
// speedup vs baseline: 5.9752x; 1.0435x over previous
#include <cuda_runtime.h>
#include <cuda_bf16.h>
#include <math.h>
#include <stdint.h>

#define BATCH 8
#define SEQ   1024
#define DIM   768
#define HEADS 12
#define HDIM  64
#define M_ROWS (BATCH*SEQ)        // 8192
#define N_QKV  (3*DIM)            // 2304
#define NKT    (DIM/32)           // 24 k-tiles of 32

#define DINLINE __device__ __forceinline__

// ---------------- scratch planes (device-code references ONLY) ----------------
#define QKV_ELEMS (BATCH*HEADS*SEQ*HDIM)
__device__ __nv_bfloat16 g_q_hi[QKV_ELEMS], g_q_lo[QKV_ELEMS];
__device__ __nv_bfloat16 g_k_hi[QKV_ELEMS], g_k_lo[QKV_ELEMS];
__device__ __nv_bfloat16 g_v_hi[QKV_ELEMS], g_v_lo[QKV_ELEMS];
__device__ __nv_bfloat16 g_o_hi[M_ROWS*DIM], g_o_lo[M_ROWS*DIM];
__device__ __nv_bfloat16 g_x_hi[M_ROWS*DIM], g_x_lo[M_ROWS*DIM];     // x split, K-major
__device__ __nv_bfloat16 g_wq_hi[N_QKV*DIM], g_wq_lo[N_QKV*DIM];     // w_qkv^T [N][K]
__device__ __nv_bfloat16 g_wp_hi[DIM*DIM],  g_wp_lo[DIM*DIM];        // w_proj^T [N][K]

// ---------------- PTX helpers ----------------
DINLINE uint32_t smem_u32(const void* p) { return (uint32_t)__cvta_generic_to_shared(p); }

DINLINE void ldsm4(uint32_t r[4], uint32_t a) {
    asm volatile("ldmatrix.sync.aligned.m8n8.x4.shared.b16 {%0,%1,%2,%3},[%4];"
                 : "=r"(r[0]), "=r"(r[1]), "=r"(r[2]), "=r"(r[3]) : "r"(a));
}
DINLINE void ldsm4t(uint32_t r[4], uint32_t a) {
    asm volatile("ldmatrix.sync.aligned.m8n8.x4.trans.shared.b16 {%0,%1,%2,%3},[%4];"
                 : "=r"(r[0]), "=r"(r[1]), "=r"(r[2]), "=r"(r[3]) : "r"(a));
}
DINLINE void mma16816(float c[4], const uint32_t a[4], const uint32_t b[2]) {
    asm volatile("mma.sync.aligned.m16n8k16.row.col.f32.bf16.bf16.f32 "
                 "{%0,%1,%2,%3},{%4,%5,%6,%7},{%8,%9},{%0,%1,%2,%3};"
                 : "+f"(c[0]), "+f"(c[1]), "+f"(c[2]), "+f"(c[3])
                 : "r"(a[0]), "r"(a[1]), "r"(a[2]), "r"(a[3]), "r"(b[0]), "r"(b[1]));
}
DINLINE void cp16(uint32_t dst, const void* src) {
    asm volatile("cp.async.cg.shared.global [%0], [%1], 16;" :: "r"(dst), "l"(src) : "memory");
}
#define CP_COMMIT() asm volatile("cp.async.commit_group;" ::: "memory")
#define CP_WAIT1()  asm volatile("cp.async.wait_group 1;" ::: "memory")

// split fp32 pair into packed bf16 hi/lo
DINLINE void split2(float x, float y, uint32_t &hi, uint32_t &lo) {
    __nv_bfloat16 hx = __float2bfloat16(x);
    __nv_bfloat16 hy = __float2bfloat16(y);
    float rx = x - __bfloat162float(hx);
    float ry = y - __bfloat162float(hy);
    __nv_bfloat162 h2; h2.x = hx; h2.y = hy;
    __nv_bfloat162 l2; l2.x = __float2bfloat16(rx); l2.y = __float2bfloat16(ry);
    hi = *reinterpret_cast<uint32_t*>(&h2);
    lo = *reinterpret_cast<uint32_t*>(&l2);
}

// ===========================================================================
// Prep kernels (write device symbols from device code only)
// ===========================================================================
__global__ __launch_bounds__(256) void split_x_kernel(const float* __restrict__ x) {
    int i = blockIdx.x * 256 + threadIdx.x;   // one float4
    float4 v = ((const float4*)x)[i];
    uint32_t h0, l0, h1, l1;
    split2(v.x, v.y, h0, l0);
    split2(v.z, v.w, h1, l1);
    ((uint2*)g_x_hi)[i] = make_uint2(h0, h1);
    ((uint2*)g_x_lo)[i] = make_uint2(l0, l1);
}

// src [K][N] fp32 -> plane set WSEL (0: w_qkv->g_wq, 1: w_proj->g_wp), [N][K] bf16 hi/lo
template <int WSEL>
__global__ __launch_bounds__(256) void tsplit_kernel(
    const float* __restrict__ src, int K, int N)
{
    __nv_bfloat16* dh = (WSEL == 0) ? g_wq_hi : g_wp_hi;
    __nv_bfloat16* dl = (WSEL == 0) ? g_wq_lo : g_wp_lo;
    __shared__ float T[32][33];
    int k0 = blockIdx.y * 32, n0 = blockIdx.x * 32;
    int tx = threadIdx.x & 31, ty = threadIdx.x >> 5;
#pragma unroll
    for (int i = 0; i < 4; i++)
        T[ty + 8 * i][tx] = src[(size_t)(k0 + ty + 8 * i) * N + n0 + tx];
    __syncthreads();
#pragma unroll
    for (int i = 0; i < 4; i++) {
        float v = T[tx][ty + 8 * i];
        __nv_bfloat16 h = __float2bfloat16(v);
        size_t o = (size_t)(n0 + ty + 8 * i) * K + k0 + tx;
        dh[o] = h;
        dl[o] = __float2bfloat16(v - __bfloat162float(h));
    }
}

// ===========================================================================
// bf16x3 mma.sync GEMM. Block 128x256, 8 warps (2x4), warp tile 64x64.
// BK=32, 3-stage cp.async pipeline. Operands resolved from device globals.
// ===========================================================================
#define PAe 40                       // smem pitch in bf16 elems (80B): conflict-free
#define A_STG (128*PAe)              // elems per A plane per stage
#define B_STG (256*PAe)
#define STG_ELEMS (2*A_STG + 2*B_STG)
#define NSTAGE 3
#define GEMM_SMEM_B (NSTAGE * STG_ELEMS * 2)   // 184320 bytes

template <bool QKV_EPI>
__global__ __launch_bounds__(256, 1) void mma_gemm_kernel(
    const float* __restrict__ bias, float* __restrict__ out)
{
    // device-code resolution of operand planes (NEVER passed from host)
    const __nv_bfloat16* Ah = QKV_EPI ? g_x_hi : g_o_hi;
    const __nv_bfloat16* Al = QKV_EPI ? g_x_lo : g_o_lo;
    const __nv_bfloat16* Bh = QKV_EPI ? g_wq_hi : g_wp_hi;
    const __nv_bfloat16* Bl = QKV_EPI ? g_wq_lo : g_wp_lo;

    extern __shared__ __nv_bfloat16 sm[];
    const int tid = threadIdx.x, lane = tid & 31, warp = tid >> 5;
    const int warp_m = warp >> 2, warp_n = warp & 3;
    const int rowBase = blockIdx.y * 128, colBase = blockIdx.x * 256;

    const int cr = tid >> 2, cc = (tid & 3) * 8;   // copy thread -> (row, elem col)

    float acc[4][8][4];
#pragma unroll
    for (int i = 0; i < 4; i++)
#pragma unroll
        for (int j = 0; j < 8; j++)
#pragma unroll
            for (int e = 0; e < 4; e++) acc[i][j][e] = 0.f;

    auto issue = [&](int st) {
        if (st < NKT) {
            const int k0 = st * 32;
            __nv_bfloat16* base = sm + (st % NSTAGE) * STG_ELEMS;
            // A: 128 rows (2 x 64 rows per pass), both planes
#pragma unroll
            for (int i = 0; i < 2; i++) {
                int r = cr + i * 64;
                uint32_t d = smem_u32(base + r * PAe + cc);
                size_t s = (size_t)(rowBase + r) * DIM + k0 + cc;
                cp16(d, Ah + s);
                cp16(d + A_STG * 2, Al + s);
            }
            // B: 256 rows (4 x 64 rows per pass), both planes
#pragma unroll
            for (int i = 0; i < 4; i++) {
                int r = cr + i * 64;
                uint32_t d = smem_u32(base + 2 * A_STG + r * PAe + cc);
                size_t s = (size_t)(colBase + r) * DIM + k0 + cc;
                cp16(d, Bh + s);
                cp16(d + B_STG * 2, Bl + s);
            }
        }
        CP_COMMIT();
    };

    issue(0);
    issue(1);

    const int a_ro = (lane & 7) + 8 * ((lane >> 3) & 1);
    const int a_co = 8 * (lane >> 4);
    const int b_ro = (lane & 7) + 8 * (lane >> 4);
    const int b_co = 8 * ((lane >> 3) & 1);

    for (int t = 0; t < NKT; t++) {
        CP_WAIT1();
        __syncthreads();
        const __nv_bfloat16* stg = sm + (t % NSTAGE) * STG_ELEMS;
        const __nv_bfloat16* sAh = stg;
        const __nv_bfloat16* sAl = stg + A_STG;
        const __nv_bfloat16* sBh = stg + 2 * A_STG;
        const __nv_bfloat16* sBl = stg + 2 * A_STG + B_STG;

#pragma unroll
        for (int ks = 0; ks < 2; ks++) {
            uint32_t afh[4][4], afl[4][4];
#pragma unroll
            for (int ma = 0; ma < 4; ma++) {
                int off = (warp_m * 64 + ma * 16 + a_ro) * PAe + ks * 16 + a_co;
                ldsm4(afh[ma], smem_u32(sAh + off));
                ldsm4(afl[ma], smem_u32(sAl + off));
            }
#pragma unroll
            for (int nb = 0; nb < 4; nb++) {
                int off = (warp_n * 64 + nb * 16 + b_ro) * PAe + ks * 16 + b_co;
                uint32_t bfh[4], bfl[4];
                ldsm4(bfh, smem_u32(sBh + off));
                ldsm4(bfl, smem_u32(sBl + off));
#pragma unroll
                for (int ma = 0; ma < 4; ma++) {
                    mma16816(acc[ma][2*nb],   afh[ma], &bfh[0]);
                    mma16816(acc[ma][2*nb+1], afh[ma], &bfh[2]);
                    mma16816(acc[ma][2*nb],   afh[ma], &bfl[0]);
                    mma16816(acc[ma][2*nb+1], afh[ma], &bfl[2]);
                    mma16816(acc[ma][2*nb],   afl[ma], &bfh[0]);
                    mma16816(acc[ma][2*nb+1], afl[ma], &bfh[2]);
                }
            }
        }
        __syncthreads();
        issue(t + 2);
    }

    // ---------------- epilogue ----------------
    const int g = lane >> 2, tq = lane & 3;
#pragma unroll
    for (int ma = 0; ma < 4; ma++) {
#pragma unroll
        for (int half = 0; half < 2; half++) {
            int row = rowBase + warp_m * 64 + ma * 16 + g + half * 8;
            if (QKV_EPI) {
                int b = row >> 10, srow = row & 1023;
#pragma unroll
                for (int nn = 0; nn < 8; nn++) {
                    int col = colBase + warp_n * 64 + nn * 8 + 2 * tq;
                    float v0 = acc[ma][nn][half * 2 + 0] + bias[col];
                    float v1 = acc[ma][nn][half * 2 + 1] + bias[col + 1];
                    int which = col / DIM;
                    int rem = col - which * DIM;
                    int h = rem >> 6, d = rem & 63;
                    size_t idx = (((size_t)(b * HEADS + h)) * SEQ + srow) * HDIM + d;
                    __nv_bfloat16* dh = (which == 0) ? g_q_hi : (which == 1) ? g_k_hi : g_v_hi;
                    __nv_bfloat16* dl = (which == 0) ? g_q_lo : (which == 1) ? g_k_lo : g_v_lo;
                    uint32_t hi, lo;
                    split2(v0, v1, hi, lo);
                    *(uint32_t*)(dh + idx) = hi;
                    *(uint32_t*)(dl + idx) = lo;
                }
            } else {
#pragma unroll
                for (int nn = 0; nn < 8; nn++) {
                    int col = colBase + warp_n * 64 + nn * 8 + 2 * tq;
                    float2 o;
                    o.x = acc[ma][nn][half * 2 + 0] + bias[col];
                    o.y = acc[ma][nn][half * 2 + 1] + bias[col + 1];
                    *(float2*)(out + (size_t)row * DIM + col) = o;
                }
            }
        }
    }
}

// ===========================================================================
// Flash attention (identical to the R2 version that passed)
// ===========================================================================
#define QPITCH 72
#define Q_PLANE (128*QPITCH)
#define KV_PLANE (64*QPITCH)
#define AT_SMEM_BYTES ((2*Q_PLANE + 4*KV_PLANE) * 2)

__global__ __launch_bounds__(256) void attn_kernel()
{
    extern __shared__ __nv_bfloat16 smb[];
    __nv_bfloat16* Qs_hi = smb;
    __nv_bfloat16* Qs_lo = Qs_hi + Q_PLANE;
    __nv_bfloat16* Ks_hi = Qs_lo + Q_PLANE;
    __nv_bfloat16* Ks_lo = Ks_hi + KV_PLANE;
    __nv_bfloat16* Vs_hi = Ks_lo + KV_PLANE;
    __nv_bfloat16* Vs_lo = Vs_hi + KV_PLANE;

    const int tid = threadIdx.x, lane = tid & 31, warp = tid >> 5;
    const int bh = blockIdx.y, qt = blockIdx.x;
    const int g = lane >> 2, t = lane & 3;
    const float scale = 0.125f;

    const size_t base = (size_t)bh * SEQ * HDIM;
    const __nv_bfloat16* qh = g_q_hi + base; const __nv_bfloat16* ql = g_q_lo + base;
    const __nv_bfloat16* kh = g_k_hi + base; const __nv_bfloat16* kl = g_k_lo + base;
    const __nv_bfloat16* vh = g_v_hi + base; const __nv_bfloat16* vl = g_v_lo + base;

#pragma unroll
    for (int i = 0; i < 4; i++) {
        int c = tid + i * 256;
        int row = c >> 3, c8 = (c & 7) * 8;
        size_t src = (size_t)(qt * 128 + row) * HDIM + c8;
        *(uint4*)(&Qs_hi[row * QPITCH + c8]) = *(const uint4*)(qh + src);
        *(uint4*)(&Qs_lo[row * QPITCH + c8]) = *(const uint4*)(ql + src);
    }

    const int kvr = tid >> 3, kvc = (tid & 7) * 8;
    uint4 pre[8];
    {
        size_t s0 = (size_t)kvr * HDIM + kvc, s1 = s0 + (size_t)32 * HDIM;
        pre[0] = *(const uint4*)(kh + s0); pre[1] = *(const uint4*)(kh + s1);
        pre[2] = *(const uint4*)(kl + s0); pre[3] = *(const uint4*)(kl + s1);
        pre[4] = *(const uint4*)(vh + s0); pre[5] = *(const uint4*)(vh + s1);
        pre[6] = *(const uint4*)(vl + s0); pre[7] = *(const uint4*)(vl + s1);
    }
    __syncthreads();

    const int a_row = warp * 16 + (lane & 7) + 8 * ((lane >> 3) & 1);
    const int a_col = 8 * (lane >> 4);
    uint32_t qfh[4][4], qfl[4][4];
#pragma unroll
    for (int ka = 0; ka < 4; ka++) {
        int off = a_row * QPITCH + ka * 16 + a_col;
        ldsm4(qfh[ka], smem_u32(&Qs_hi[off]));
        ldsm4(qfl[ka], smem_u32(&Qs_lo[off]));
    }

    const int k_row = (lane & 7) + 8 * (lane >> 4);
    const int k_col = 8 * ((lane >> 3) & 1);
    const int v_row = (lane & 7) + 8 * ((lane >> 3) & 1);
    const int v_col = 8 * (lane >> 4);

    float m0 = -1e30f, m1 = -1e30f, l0 = 0.f, l1 = 0.f;
    float o[8][4];
#pragma unroll
    for (int j = 0; j < 8; j++)
#pragma unroll
        for (int e = 0; e < 4; e++) o[j][e] = 0.f;

    for (int kt = 0; kt < SEQ / 64; kt++) {
        __syncthreads();
        *(uint4*)(&Ks_hi[kvr * QPITCH + kvc]) = pre[0];
        *(uint4*)(&Ks_hi[(kvr + 32) * QPITCH + kvc]) = pre[1];
        *(uint4*)(&Ks_lo[kvr * QPITCH + kvc]) = pre[2];
        *(uint4*)(&Ks_lo[(kvr + 32) * QPITCH + kvc]) = pre[3];
        *(uint4*)(&Vs_hi[kvr * QPITCH + kvc]) = pre[4];
        *(uint4*)(&Vs_hi[(kvr + 32) * QPITCH + kvc]) = pre[5];
        *(uint4*)(&Vs_lo[kvr * QPITCH + kvc]) = pre[6];
        *(uint4*)(&Vs_lo[(kvr + 32) * QPITCH + kvc]) = pre[7];
        __syncthreads();
        if (kt + 1 < SEQ / 64) {
            size_t s0 = (size_t)((kt + 1) * 64 + kvr) * HDIM + kvc;
            size_t s1 = s0 + (size_t)32 * HDIM;
            pre[0] = *(const uint4*)(kh + s0); pre[1] = *(const uint4*)(kh + s1);
            pre[2] = *(const uint4*)(kl + s0); pre[3] = *(const uint4*)(kl + s1);
            pre[4] = *(const uint4*)(vh + s0); pre[5] = *(const uint4*)(vh + s1);
            pre[6] = *(const uint4*)(vl + s0); pre[7] = *(const uint4*)(vl + s1);
        }

        float s[8][4];
#pragma unroll
        for (int j = 0; j < 8; j++)
#pragma unroll
            for (int e = 0; e < 4; e++) s[j][e] = 0.f;

#pragma unroll
        for (int nb = 0; nb < 4; nb++) {
#pragma unroll
            for (int ka = 0; ka < 4; ka++) {
                int off = (nb * 16 + k_row) * QPITCH + ka * 16 + k_col;
                uint32_t kfh[4], kfl[4];
                ldsm4(kfh, smem_u32(&Ks_hi[off]));
                ldsm4(kfl, smem_u32(&Ks_lo[off]));
                mma16816(s[2*nb],   qfh[ka], &kfh[0]);
                mma16816(s[2*nb+1], qfh[ka], &kfh[2]);
                mma16816(s[2*nb],   qfh[ka], &kfl[0]);
                mma16816(s[2*nb+1], qfh[ka], &kfl[2]);
                mma16816(s[2*nb],   qfl[ka], &kfh[0]);
                mma16816(s[2*nb+1], qfl[ka], &kfh[2]);
            }
        }

        float mx0 = -1e30f, mx1 = -1e30f;
#pragma unroll
        for (int j = 0; j < 8; j++) {
            s[j][0] *= scale; s[j][1] *= scale; s[j][2] *= scale; s[j][3] *= scale;
            mx0 = fmaxf(mx0, fmaxf(s[j][0], s[j][1]));
            mx1 = fmaxf(mx1, fmaxf(s[j][2], s[j][3]));
        }
        mx0 = fmaxf(mx0, __shfl_xor_sync(0xffffffffu, mx0, 1));
        mx0 = fmaxf(mx0, __shfl_xor_sync(0xffffffffu, mx0, 2));
        mx1 = fmaxf(mx1, __shfl_xor_sync(0xffffffffu, mx1, 1));
        mx1 = fmaxf(mx1, __shfl_xor_sync(0xffffffffu, mx1, 2));
        float mn0 = fmaxf(m0, mx0), mn1 = fmaxf(m1, mx1);
        float c0 = __expf(m0 - mn0), c1 = __expf(m1 - mn1);
        float p[8][4];
        float ls0 = 0.f, ls1 = 0.f;
#pragma unroll
        for (int j = 0; j < 8; j++) {
            p[j][0] = __expf(s[j][0] - mn0); p[j][1] = __expf(s[j][1] - mn0);
            p[j][2] = __expf(s[j][2] - mn1); p[j][3] = __expf(s[j][3] - mn1);
            ls0 += p[j][0] + p[j][1];
            ls1 += p[j][2] + p[j][3];
        }
        ls0 += __shfl_xor_sync(0xffffffffu, ls0, 1);
        ls0 += __shfl_xor_sync(0xffffffffu, ls0, 2);
        ls1 += __shfl_xor_sync(0xffffffffu, ls1, 1);
        ls1 += __shfl_xor_sync(0xffffffffu, ls1, 2);
        l0 = l0 * c0 + ls0; m0 = mn0;
        l1 = l1 * c1 + ls1; m1 = mn1;
#pragma unroll
        for (int j = 0; j < 8; j++) {
            o[j][0] *= c0; o[j][1] *= c0; o[j][2] *= c1; o[j][3] *= c1;
        }

        uint32_t pfh[4][4], pfl[4][4];
#pragma unroll
        for (int ka = 0; ka < 4; ka++) {
            split2(p[2*ka][0],   p[2*ka][1],   pfh[ka][0], pfl[ka][0]);
            split2(p[2*ka][2],   p[2*ka][3],   pfh[ka][1], pfl[ka][1]);
            split2(p[2*ka+1][0], p[2*ka+1][1], pfh[ka][2], pfl[ka][2]);
            split2(p[2*ka+1][2], p[2*ka+1][3], pfh[ka][3], pfl[ka][3]);
        }

#pragma unroll
        for (int nb = 0; nb < 4; nb++) {
#pragma unroll
            for (int ka = 0; ka < 4; ka++) {
                int off = (ka * 16 + v_row) * QPITCH + nb * 16 + v_col;
                uint32_t vfh[4], vfl[4];
                ldsm4t(vfh, smem_u32(&Vs_hi[off]));
                ldsm4t(vfl, smem_u32(&Vs_lo[off]));
                mma16816(o[2*nb],   pfh[ka], &vfh[0]);
                mma16816(o[2*nb+1], pfh[ka], &vfh[2]);
                mma16816(o[2*nb],   pfh[ka], &vfl[0]);
                mma16816(o[2*nb+1], pfh[ka], &vfl[2]);
                mma16816(o[2*nb],   pfl[ka], &vfh[0]);
                mma16816(o[2*nb+1], pfl[ka], &vfh[2]);
            }
        }
    }

    float i0 = 1.f / l0, i1 = 1.f / l1;
    int b = bh / HEADS, h = bh - (bh / HEADS) * HEADS;
    int srow0 = qt * 128 + warp * 16 + g;
    int srow1 = srow0 + 8;
#pragma unroll
    for (int j = 0; j < 8; j++) {
        int col = h * HDIM + j * 8 + 2 * t;
        size_t i0x = ((size_t)(b * SEQ) + srow0) * DIM + col;
        size_t i1x = ((size_t)(b * SEQ) + srow1) * DIM + col;
        uint32_t hi, lo;
        split2(o[j][0] * i0, o[j][1] * i0, hi, lo);
        *(uint32_t*)(g_o_hi + i0x) = hi;
        *(uint32_t*)(g_o_lo + i0x) = lo;
        split2(o[j][2] * i1, o[j][3] * i1, hi, lo);
        *(uint32_t*)(g_o_hi + i1x) = hi;
        *(uint32_t*)(g_o_lo + i1x) = lo;
    }
}

// ===========================================================================
extern "C" void kernel_launch(void* const* d_in, const int* in_sizes, int n_in,
                              void* d_out, int out_size) {
    const float* x      = (const float*)d_in[0];
    const float* w_qkv  = (const float*)d_in[1];
    const float* b_qkv  = (const float*)d_in[2];
    const float* w_proj = (const float*)d_in[3];
    const float* b_proj = (const float*)d_in[4];
    float* out = (float*)d_out;

    cudaFuncSetAttribute(attn_kernel, cudaFuncAttributeMaxDynamicSharedMemorySize,
                         AT_SMEM_BYTES);
    cudaFuncSetAttribute(mma_gemm_kernel<true>, cudaFuncAttributeMaxDynamicSharedMemorySize,
                         GEMM_SMEM_B);
    cudaFuncSetAttribute(mma_gemm_kernel<false>, cudaFuncAttributeMaxDynamicSharedMemorySize,
                         GEMM_SMEM_B);

    // prep: split x, transpose+split weights (destinations resolved in device code)
    split_x_kernel<<<M_ROWS * DIM / 1024, 256>>>(x);
    tsplit_kernel<0><<<dim3(N_QKV / 32, DIM / 32), 256>>>(w_qkv, DIM, N_QKV);
    tsplit_kernel<1><<<dim3(DIM / 32, DIM / 32), 256>>>(w_proj, DIM, DIM);

    // QKV GEMM: M=8192, N=2304
    mma_gemm_kernel<true><<<dim3(N_QKV / 256, M_ROWS / 128), 256, GEMM_SMEM_B>>>(
        b_qkv, nullptr);

    // attention
    attn_kernel<<<dim3(SEQ / 128, BATCH * HEADS), 256, AT_SMEM_BYTES>>>();

    // proj GEMM: M=8192, N=768
    mma_gemm_kernel<false><<<dim3(DIM / 256, M_ROWS / 128), 256, GEMM_SMEM_B>>>(
        b_proj, out);
}

// round 7
// speedup vs baseline: 6.3928x; 1.0699x over previous
#include <cuda_runtime.h>
#include <cuda_bf16.h>
#include <math.h>
#include <stdint.h>

#define BATCH 8
#define SEQ   1024
#define DIM   768
#define HEADS 12
#define HDIM  64
#define M_ROWS (BATCH*SEQ)        // 8192
#define N_QKV  (3*DIM)            // 2304
#define NKT    (DIM/32)           // 24 k-tiles of 32

#define DINLINE __device__ __forceinline__

// ---------------- scratch planes (device-code references ONLY) ----------------
#define QKV_ELEMS (BATCH*HEADS*SEQ*HDIM)
__device__ __nv_bfloat16 g_q_hi[QKV_ELEMS], g_q_lo[QKV_ELEMS];
__device__ __nv_bfloat16 g_k_hi[QKV_ELEMS], g_k_lo[QKV_ELEMS];
__device__ __nv_bfloat16 g_v_hi[QKV_ELEMS], g_v_lo[QKV_ELEMS];
__device__ __nv_bfloat16 g_o_hi[M_ROWS*DIM], g_o_lo[M_ROWS*DIM];
__device__ __nv_bfloat16 g_x_hi[M_ROWS*DIM], g_x_lo[M_ROWS*DIM];     // x split, K-major
__device__ __nv_bfloat16 g_wq_hi[N_QKV*DIM], g_wq_lo[N_QKV*DIM];     // w_qkv^T [N][K]
__device__ __nv_bfloat16 g_wp_hi[DIM*DIM],  g_wp_lo[DIM*DIM];        // w_proj^T [N][K]

// ---------------- PTX helpers ----------------
DINLINE uint32_t smem_u32(const void* p) { return (uint32_t)__cvta_generic_to_shared(p); }

DINLINE void ldsm4(uint32_t r[4], uint32_t a) {
    asm volatile("ldmatrix.sync.aligned.m8n8.x4.shared.b16 {%0,%1,%2,%3},[%4];"
                 : "=r"(r[0]), "=r"(r[1]), "=r"(r[2]), "=r"(r[3]) : "r"(a));
}
DINLINE void ldsm4t(uint32_t r[4], uint32_t a) {
    asm volatile("ldmatrix.sync.aligned.m8n8.x4.trans.shared.b16 {%0,%1,%2,%3},[%4];"
                 : "=r"(r[0]), "=r"(r[1]), "=r"(r[2]), "=r"(r[3]) : "r"(a));
}
DINLINE void mma16816(float c[4], const uint32_t a[4], const uint32_t b[2]) {
    asm volatile("mma.sync.aligned.m16n8k16.row.col.f32.bf16.bf16.f32 "
                 "{%0,%1,%2,%3},{%4,%5,%6,%7},{%8,%9},{%0,%1,%2,%3};"
                 : "+f"(c[0]), "+f"(c[1]), "+f"(c[2]), "+f"(c[3])
                 : "r"(a[0]), "r"(a[1]), "r"(a[2]), "r"(a[3]), "r"(b[0]), "r"(b[1]));
}
DINLINE void cp16(uint32_t dst, const void* src) {
    asm volatile("cp.async.cg.shared.global [%0], [%1], 16;" :: "r"(dst), "l"(src) : "memory");
}
#define CP_COMMIT() asm volatile("cp.async.commit_group;" ::: "memory")
#define CP_WAIT1()  asm volatile("cp.async.wait_group 1;" ::: "memory")

// split fp32 pair into packed bf16 hi/lo
DINLINE void split2(float x, float y, uint32_t &hi, uint32_t &lo) {
    __nv_bfloat16 hx = __float2bfloat16(x);
    __nv_bfloat16 hy = __float2bfloat16(y);
    float rx = x - __bfloat162float(hx);
    float ry = y - __bfloat162float(hy);
    __nv_bfloat162 h2; h2.x = hx; h2.y = hy;
    __nv_bfloat162 l2; l2.x = __float2bfloat16(rx); l2.y = __float2bfloat16(ry);
    hi = *reinterpret_cast<uint32_t*>(&h2);
    lo = *reinterpret_cast<uint32_t*>(&l2);
}

// ===========================================================================
// Prep kernels (write device symbols from device code only)
// ===========================================================================
__global__ __launch_bounds__(256) void split_x_kernel(const float* __restrict__ x) {
    int i = blockIdx.x * 256 + threadIdx.x;   // one float4
    float4 v = ((const float4*)x)[i];
    uint32_t h0, l0, h1, l1;
    split2(v.x, v.y, h0, l0);
    split2(v.z, v.w, h1, l1);
    ((uint2*)g_x_hi)[i] = make_uint2(h0, h1);
    ((uint2*)g_x_lo)[i] = make_uint2(l0, l1);
}

// src [K][N] fp32 -> plane set WSEL (0: w_qkv->g_wq, 1: w_proj->g_wp), [N][K] bf16 hi/lo
template <int WSEL>
__global__ __launch_bounds__(256) void tsplit_kernel(
    const float* __restrict__ src, int K, int N)
{
    __nv_bfloat16* dh = (WSEL == 0) ? g_wq_hi : g_wp_hi;
    __nv_bfloat16* dl = (WSEL == 0) ? g_wq_lo : g_wp_lo;
    __shared__ float T[32][33];
    int k0 = blockIdx.y * 32, n0 = blockIdx.x * 32;
    int tx = threadIdx.x & 31, ty = threadIdx.x >> 5;
#pragma unroll
    for (int i = 0; i < 4; i++)
        T[ty + 8 * i][tx] = src[(size_t)(k0 + ty + 8 * i) * N + n0 + tx];
    __syncthreads();
#pragma unroll
    for (int i = 0; i < 4; i++) {
        float v = T[tx][ty + 8 * i];
        __nv_bfloat16 h = __float2bfloat16(v);
        size_t o = (size_t)(n0 + ty + 8 * i) * K + k0 + tx;
        dh[o] = h;
        dl[o] = __float2bfloat16(v - __bfloat162float(h));
    }
}

// ===========================================================================
// bf16x3 mma.sync GEMM. Block 64x256, 4 warps, warp tile 64x64.
// BK=32, 2-stage cp.async pipeline, 2 CTAs/SM for cross-CTA overlap.
// ===========================================================================
#define PAe 40                       // smem pitch in bf16 elems (80B): conflict-free
#define A_STG (64*PAe)               // elems per A plane per stage
#define B_STG (256*PAe)
#define STG_ELEMS (2*A_STG + 2*B_STG)          // 25600 elems
#define NSTAGE 2
#define GEMM_SMEM_B (NSTAGE * STG_ELEMS * 2)   // 102400 bytes

template <bool QKV_EPI>
__global__ __launch_bounds__(128, 2) void mma_gemm_kernel(
    const float* __restrict__ bias, float* __restrict__ out)
{
    // device-code resolution of operand planes (NEVER passed from host)
    const __nv_bfloat16* Ah = QKV_EPI ? g_x_hi : g_o_hi;
    const __nv_bfloat16* Al = QKV_EPI ? g_x_lo : g_o_lo;
    const __nv_bfloat16* Bh = QKV_EPI ? g_wq_hi : g_wp_hi;
    const __nv_bfloat16* Bl = QKV_EPI ? g_wq_lo : g_wp_lo;

    extern __shared__ __nv_bfloat16 sm[];
    const int tid = threadIdx.x, lane = tid & 31, warp = tid >> 5;
    const int rowBase = blockIdx.y * 64, colBase = blockIdx.x * 256;

    float acc[4][8][4];
#pragma unroll
    for (int i = 0; i < 4; i++)
#pragma unroll
        for (int j = 0; j < 8; j++)
#pragma unroll
            for (int e = 0; e < 4; e++) acc[i][j][e] = 0.f;

    auto issue = [&](int st) {
        if (st < NKT) {
            const int k0 = st * 32;
            __nv_bfloat16* base = sm + (st & 1) * STG_ELEMS;
            // A: 64 rows x 32 cols = 256 chunks/plane, 128 thr -> 2 each
#pragma unroll
            for (int i = 0; i < 2; i++) {
                int id = tid + i * 128;
                int r = id >> 2, c8 = (id & 3) * 8;
                uint32_t d = smem_u32(base + r * PAe + c8);
                size_t s = (size_t)(rowBase + r) * DIM + k0 + c8;
                cp16(d, Ah + s);
                cp16(d + A_STG * 2, Al + s);
            }
            // B: 256 rows x 32 cols = 1024 chunks/plane -> 8 each
#pragma unroll
            for (int i = 0; i < 8; i++) {
                int id = tid + i * 128;
                int r = id >> 2, c8 = (id & 3) * 8;
                uint32_t d = smem_u32(base + 2 * A_STG + r * PAe + c8);
                size_t s = (size_t)(colBase + r) * DIM + k0 + c8;
                cp16(d, Bh + s);
                cp16(d + B_STG * 2, Bl + s);
            }
        }
        CP_COMMIT();
    };

    issue(0);
    issue(1);

    const int a_ro = (lane & 7) + 8 * ((lane >> 3) & 1);
    const int a_co = 8 * (lane >> 4);
    const int b_ro = (lane & 7) + 8 * (lane >> 4);
    const int b_co = 8 * ((lane >> 3) & 1);

    for (int t = 0; t < NKT; t++) {
        CP_WAIT1();
        __syncthreads();
        const __nv_bfloat16* stg = sm + (t & 1) * STG_ELEMS;
        const __nv_bfloat16* sAh = stg;
        const __nv_bfloat16* sAl = stg + A_STG;
        const __nv_bfloat16* sBh = stg + 2 * A_STG;
        const __nv_bfloat16* sBl = stg + 2 * A_STG + B_STG;

#pragma unroll
        for (int ks = 0; ks < 2; ks++) {
            uint32_t afh[4][4], afl[4][4];
#pragma unroll
            for (int ma = 0; ma < 4; ma++) {
                int off = (ma * 16 + a_ro) * PAe + ks * 16 + a_co;
                ldsm4(afh[ma], smem_u32(sAh + off));
                ldsm4(afl[ma], smem_u32(sAl + off));
            }
#pragma unroll
            for (int nb = 0; nb < 4; nb++) {
                int off = (warp * 64 + nb * 16 + b_ro) * PAe + ks * 16 + b_co;
                uint32_t bfh[4], bfl[4];
                ldsm4(bfh, smem_u32(sBh + off));
                ldsm4(bfl, smem_u32(sBl + off));
#pragma unroll
                for (int ma = 0; ma < 4; ma++) {
                    mma16816(acc[ma][2*nb],   afh[ma], &bfh[0]);
                    mma16816(acc[ma][2*nb+1], afh[ma], &bfh[2]);
                    mma16816(acc[ma][2*nb],   afh[ma], &bfl[0]);
                    mma16816(acc[ma][2*nb+1], afh[ma], &bfl[2]);
                    mma16816(acc[ma][2*nb],   afl[ma], &bfh[0]);
                    mma16816(acc[ma][2*nb+1], afl[ma], &bfh[2]);
                }
            }
        }
        __syncthreads();
        issue(t + 2);
    }

    // ---------------- epilogue ----------------
    const int g = lane >> 2, tq = lane & 3;
#pragma unroll
    for (int ma = 0; ma < 4; ma++) {
#pragma unroll
        for (int half = 0; half < 2; half++) {
            int row = rowBase + ma * 16 + g + half * 8;
            if (QKV_EPI) {
                int b = row >> 10, srow = row & 1023;
#pragma unroll
                for (int nn = 0; nn < 8; nn++) {
                    int col = colBase + warp * 64 + nn * 8 + 2 * tq;
                    float v0 = acc[ma][nn][half * 2 + 0] + bias[col];
                    float v1 = acc[ma][nn][half * 2 + 1] + bias[col + 1];
                    int which = col / DIM;
                    int rem = col - which * DIM;
                    int h = rem >> 6, d = rem & 63;
                    size_t idx = (((size_t)(b * HEADS + h)) * SEQ + srow) * HDIM + d;
                    __nv_bfloat16* dh = (which == 0) ? g_q_hi : (which == 1) ? g_k_hi : g_v_hi;
                    __nv_bfloat16* dl = (which == 0) ? g_q_lo : (which == 1) ? g_k_lo : g_v_lo;
                    uint32_t hi, lo;
                    split2(v0, v1, hi, lo);
                    *(uint32_t*)(dh + idx) = hi;
                    *(uint32_t*)(dl + idx) = lo;
                }
            } else {
#pragma unroll
                for (int nn = 0; nn < 8; nn++) {
                    int col = colBase + warp * 64 + nn * 8 + 2 * tq;
                    float2 o;
                    o.x = acc[ma][nn][half * 2 + 0] + bias[col];
                    o.y = acc[ma][nn][half * 2 + 1] + bias[col + 1];
                    *(float2*)(out + (size_t)row * DIM + col) = o;
                }
            }
        }
    }
}

// ===========================================================================
// Flash attention (identical to the passing R6 version)
// ===========================================================================
#define QPITCH 72
#define Q_PLANE (128*QPITCH)
#define KV_PLANE (64*QPITCH)
#define AT_SMEM_BYTES ((2*Q_PLANE + 4*KV_PLANE) * 2)

__global__ __launch_bounds__(256) void attn_kernel()
{
    extern __shared__ __nv_bfloat16 smb[];
    __nv_bfloat16* Qs_hi = smb;
    __nv_bfloat16* Qs_lo = Qs_hi + Q_PLANE;
    __nv_bfloat16* Ks_hi = Qs_lo + Q_PLANE;
    __nv_bfloat16* Ks_lo = Ks_hi + KV_PLANE;
    __nv_bfloat16* Vs_hi = Ks_lo + KV_PLANE;
    __nv_bfloat16* Vs_lo = Vs_hi + KV_PLANE;

    const int tid = threadIdx.x, lane = tid & 31, warp = tid >> 5;
    const int bh = blockIdx.y, qt = blockIdx.x;
    const int g = lane >> 2, t = lane & 3;
    const float scale = 0.125f;

    const size_t base = (size_t)bh * SEQ * HDIM;
    const __nv_bfloat16* qh = g_q_hi + base; const __nv_bfloat16* ql = g_q_lo + base;
    const __nv_bfloat16* kh = g_k_hi + base; const __nv_bfloat16* kl = g_k_lo + base;
    const __nv_bfloat16* vh = g_v_hi + base; const __nv_bfloat16* vl = g_v_lo + base;

#pragma unroll
    for (int i = 0; i < 4; i++) {
        int c = tid + i * 256;
        int row = c >> 3, c8 = (c & 7) * 8;
        size_t src = (size_t)(qt * 128 + row) * HDIM + c8;
        *(uint4*)(&Qs_hi[row * QPITCH + c8]) = *(const uint4*)(qh + src);
        *(uint4*)(&Qs_lo[row * QPITCH + c8]) = *(const uint4*)(ql + src);
    }

    const int kvr = tid >> 3, kvc = (tid & 7) * 8;
    uint4 pre[8];
    {
        size_t s0 = (size_t)kvr * HDIM + kvc, s1 = s0 + (size_t)32 * HDIM;
        pre[0] = *(const uint4*)(kh + s0); pre[1] = *(const uint4*)(kh + s1);
        pre[2] = *(const uint4*)(kl + s0); pre[3] = *(const uint4*)(kl + s1);
        pre[4] = *(const uint4*)(vh + s0); pre[5] = *(const uint4*)(vh + s1);
        pre[6] = *(const uint4*)(vl + s0); pre[7] = *(const uint4*)(vl + s1);
    }
    __syncthreads();

    const int a_row = warp * 16 + (lane & 7) + 8 * ((lane >> 3) & 1);
    const int a_col = 8 * (lane >> 4);
    uint32_t qfh[4][4], qfl[4][4];
#pragma unroll
    for (int ka = 0; ka < 4; ka++) {
        int off = a_row * QPITCH + ka * 16 + a_col;
        ldsm4(qfh[ka], smem_u32(&Qs_hi[off]));
        ldsm4(qfl[ka], smem_u32(&Qs_lo[off]));
    }

    const int k_row = (lane & 7) + 8 * (lane >> 4);
    const int k_col = 8 * ((lane >> 3) & 1);
    const int v_row = (lane & 7) + 8 * ((lane >> 3) & 1);
    const int v_col = 8 * (lane >> 4);

    float m0 = -1e30f, m1 = -1e30f, l0 = 0.f, l1 = 0.f;
    float o[8][4];
#pragma unroll
    for (int j = 0; j < 8; j++)
#pragma unroll
        for (int e = 0; e < 4; e++) o[j][e] = 0.f;

    for (int kt = 0; kt < SEQ / 64; kt++) {
        __syncthreads();
        *(uint4*)(&Ks_hi[kvr * QPITCH + kvc]) = pre[0];
        *(uint4*)(&Ks_hi[(kvr + 32) * QPITCH + kvc]) = pre[1];
        *(uint4*)(&Ks_lo[kvr * QPITCH + kvc]) = pre[2];
        *(uint4*)(&Ks_lo[(kvr + 32) * QPITCH + kvc]) = pre[3];
        *(uint4*)(&Vs_hi[kvr * QPITCH + kvc]) = pre[4];
        *(uint4*)(&Vs_hi[(kvr + 32) * QPITCH + kvc]) = pre[5];
        *(uint4*)(&Vs_lo[kvr * QPITCH + kvc]) = pre[6];
        *(uint4*)(&Vs_lo[(kvr + 32) * QPITCH + kvc]) = pre[7];
        __syncthreads();
        if (kt + 1 < SEQ / 64) {
            size_t s0 = (size_t)((kt + 1) * 64 + kvr) * HDIM + kvc;
            size_t s1 = s0 + (size_t)32 * HDIM;
            pre[0] = *(const uint4*)(kh + s0); pre[1] = *(const uint4*)(kh + s1);
            pre[2] = *(const uint4*)(kl + s0); pre[3] = *(const uint4*)(kl + s1);
            pre[4] = *(const uint4*)(vh + s0); pre[5] = *(const uint4*)(vh + s1);
            pre[6] = *(const uint4*)(vl + s0); pre[7] = *(const uint4*)(vl + s1);
        }

        float s[8][4];
#pragma unroll
        for (int j = 0; j < 8; j++)
#pragma unroll
            for (int e = 0; e < 4; e++) s[j][e] = 0.f;

#pragma unroll
        for (int nb = 0; nb < 4; nb++) {
#pragma unroll
            for (int ka = 0; ka < 4; ka++) {
                int off = (nb * 16 + k_row) * QPITCH + ka * 16 + k_col;
                uint32_t kfh[4], kfl[4];
                ldsm4(kfh, smem_u32(&Ks_hi[off]));
                ldsm4(kfl, smem_u32(&Ks_lo[off]));
                mma16816(s[2*nb],   qfh[ka], &kfh[0]);
                mma16816(s[2*nb+1], qfh[ka], &kfh[2]);
                mma16816(s[2*nb],   qfh[ka], &kfl[0]);
                mma16816(s[2*nb+1], qfh[ka], &kfl[2]);
                mma16816(s[2*nb],   qfl[ka], &kfh[0]);
                mma16816(s[2*nb+1], qfl[ka], &kfh[2]);
            }
        }

        float mx0 = -1e30f, mx1 = -1e30f;
#pragma unroll
        for (int j = 0; j < 8; j++) {
            s[j][0] *= scale; s[j][1] *= scale; s[j][2] *= scale; s[j][3] *= scale;
            mx0 = fmaxf(mx0, fmaxf(s[j][0], s[j][1]));
            mx1 = fmaxf(mx1, fmaxf(s[j][2], s[j][3]));
        }
        mx0 = fmaxf(mx0, __shfl_xor_sync(0xffffffffu, mx0, 1));
        mx0 = fmaxf(mx0, __shfl_xor_sync(0xffffffffu, mx0, 2));
        mx1 = fmaxf(mx1, __shfl_xor_sync(0xffffffffu, mx1, 1));
        mx1 = fmaxf(mx1, __shfl_xor_sync(0xffffffffu, mx1, 2));
        float mn0 = fmaxf(m0, mx0), mn1 = fmaxf(m1, mx1);
        float c0 = __expf(m0 - mn0), c1 = __expf(m1 - mn1);
        float p[8][4];
        float ls0 = 0.f, ls1 = 0.f;
#pragma unroll
        for (int j = 0; j < 8; j++) {
            p[j][0] = __expf(s[j][0] - mn0); p[j][1] = __expf(s[j][1] - mn0);
            p[j][2] = __expf(s[j][2] - mn1); p[j][3] = __expf(s[j][3] - mn1);
            ls0 += p[j][0] + p[j][1];
            ls1 += p[j][2] + p[j][3];
        }
        ls0 += __shfl_xor_sync(0xffffffffu, ls0, 1);
        ls0 += __shfl_xor_sync(0xffffffffu, ls0, 2);
        ls1 += __shfl_xor_sync(0xffffffffu, ls1, 1);
        ls1 += __shfl_xor_sync(0xffffffffu, ls1, 2);
        l0 = l0 * c0 + ls0; m0 = mn0;
        l1 = l1 * c1 + ls1; m1 = mn1;
#pragma unroll
        for (int j = 0; j < 8; j++) {
            o[j][0] *= c0; o[j][1] *= c0; o[j][2] *= c1; o[j][3] *= c1;
        }

        uint32_t pfh[4][4], pfl[4][4];
#pragma unroll
        for (int ka = 0; ka < 4; ka++) {
            split2(p[2*ka][0],   p[2*ka][1],   pfh[ka][0], pfl[ka][0]);
            split2(p[2*ka][2],   p[2*ka][3],   pfh[ka][1], pfl[ka][1]);
            split2(p[2*ka+1][0], p[2*ka+1][1], pfh[ka][2], pfl[ka][2]);
            split2(p[2*ka+1][2], p[2*ka+1][3], pfh[ka][3], pfl[ka][3]);
        }

#pragma unroll
        for (int nb = 0; nb < 4; nb++) {
#pragma unroll
            for (int ka = 0; ka < 4; ka++) {
                int off = (ka * 16 + v_row) * QPITCH + nb * 16 + v_col;
                uint32_t vfh[4], vfl[4];
                ldsm4t(vfh, smem_u32(&Vs_hi[off]));
                ldsm4t(vfl, smem_u32(&Vs_lo[off]));
                mma16816(o[2*nb],   pfh[ka], &vfh[0]);
                mma16816(o[2*nb+1], pfh[ka], &vfh[2]);
                mma16816(o[2*nb],   pfh[ka], &vfl[0]);
                mma16816(o[2*nb+1], pfh[ka], &vfl[2]);
                mma16816(o[2*nb],   pfl[ka], &vfh[0]);
                mma16816(o[2*nb+1], pfl[ka], &vfh[2]);
            }
        }
    }

    float i0 = 1.f / l0, i1 = 1.f / l1;
    int b = bh / HEADS, h = bh - (bh / HEADS) * HEADS;
    int srow0 = qt * 128 + warp * 16 + g;
    int srow1 = srow0 + 8;
#pragma unroll
    for (int j = 0; j < 8; j++) {
        int col = h * HDIM + j * 8 + 2 * t;
        size_t i0x = ((size_t)(b * SEQ) + srow0) * DIM + col;
        size_t i1x = ((size_t)(b * SEQ) + srow1) * DIM + col;
        uint32_t hi, lo;
        split2(o[j][0] * i0, o[j][1] * i0, hi, lo);
        *(uint32_t*)(g_o_hi + i0x) = hi;
        *(uint32_t*)(g_o_lo + i0x) = lo;
        split2(o[j][2] * i1, o[j][3] * i1, hi, lo);
        *(uint32_t*)(g_o_hi + i1x) = hi;
        *(uint32_t*)(g_o_lo + i1x) = lo;
    }
}

// ===========================================================================
extern "C" void kernel_launch(void* const* d_in, const int* in_sizes, int n_in,
                              void* d_out, int out_size) {
    const float* x      = (const float*)d_in[0];
    const float* w_qkv  = (const float*)d_in[1];
    const float* b_qkv  = (const float*)d_in[2];
    const float* w_proj = (const float*)d_in[3];
    const float* b_proj = (const float*)d_in[4];
    float* out = (float*)d_out;

    cudaFuncSetAttribute(attn_kernel, cudaFuncAttributeMaxDynamicSharedMemorySize,
                         AT_SMEM_BYTES);
    cudaFuncSetAttribute(mma_gemm_kernel<true>, cudaFuncAttributeMaxDynamicSharedMemorySize,
                         GEMM_SMEM_B);
    cudaFuncSetAttribute(mma_gemm_kernel<false>, cudaFuncAttributeMaxDynamicSharedMemorySize,
                         GEMM_SMEM_B);

    // prep: split x, transpose+split weights (destinations resolved in device code)
    split_x_kernel<<<M_ROWS * DIM / 1024, 256>>>(x);
    tsplit_kernel<0><<<dim3(N_QKV / 32, DIM / 32), 256>>>(w_qkv, DIM, N_QKV);
    tsplit_kernel<1><<<dim3(DIM / 32, DIM / 32), 256>>>(w_proj, DIM, DIM);

    // QKV GEMM: M=8192, N=2304
    mma_gemm_kernel<true><<<dim3(N_QKV / 256, M_ROWS / 64), 128, GEMM_SMEM_B>>>(
        b_qkv, nullptr);

    // attention
    attn_kernel<<<dim3(SEQ / 128, BATCH * HEADS), 256, AT_SMEM_BYTES>>>();

    // proj GEMM: M=8192, N=768
    mma_gemm_kernel<false><<<dim3(DIM / 256, M_ROWS / 64), 128, GEMM_SMEM_B>>>(
        b_proj, out);
}

// round 8
// speedup vs baseline: 6.5110x; 1.0185x over previous
#include <cuda_runtime.h>
#include <cuda_bf16.h>
#include <math.h>
#include <stdint.h>

#define BATCH 8
#define SEQ   1024
#define DIM   768
#define HEADS 12
#define HDIM  64
#define M_ROWS (BATCH*SEQ)        // 8192
#define N_QKV  (3*DIM)            // 2304
#define NKT    (DIM/32)           // 24 k-tiles of 32

#define DINLINE __device__ __forceinline__

// ---------------- scratch planes (device-code references ONLY) ----------------
#define QKV_ELEMS (BATCH*HEADS*SEQ*HDIM)
__device__ __nv_bfloat16 g_q_hi[QKV_ELEMS], g_q_lo[QKV_ELEMS];
__device__ __nv_bfloat16 g_k_hi[QKV_ELEMS], g_k_lo[QKV_ELEMS];
__device__ __nv_bfloat16 g_v_hi[QKV_ELEMS], g_v_lo[QKV_ELEMS];
__device__ __nv_bfloat16 g_o_hi[M_ROWS*DIM], g_o_lo[M_ROWS*DIM];
__device__ __nv_bfloat16 g_x_hi[M_ROWS*DIM], g_x_lo[M_ROWS*DIM];     // x split, K-major
__device__ __nv_bfloat16 g_wq_hi[N_QKV*DIM], g_wq_lo[N_QKV*DIM];     // w_qkv^T [N][K]
__device__ __nv_bfloat16 g_wp_hi[DIM*DIM],  g_wp_lo[DIM*DIM];        // w_proj^T [N][K]

// ---------------- PTX helpers ----------------
DINLINE uint32_t smem_u32(const void* p) { return (uint32_t)__cvta_generic_to_shared(p); }

DINLINE void ldsm4(uint32_t r[4], uint32_t a) {
    asm volatile("ldmatrix.sync.aligned.m8n8.x4.shared.b16 {%0,%1,%2,%3},[%4];"
                 : "=r"(r[0]), "=r"(r[1]), "=r"(r[2]), "=r"(r[3]) : "r"(a));
}
DINLINE void ldsm4t(uint32_t r[4], uint32_t a) {
    asm volatile("ldmatrix.sync.aligned.m8n8.x4.trans.shared.b16 {%0,%1,%2,%3},[%4];"
                 : "=r"(r[0]), "=r"(r[1]), "=r"(r[2]), "=r"(r[3]) : "r"(a));
}
DINLINE void mma16816(float c[4], const uint32_t a[4], const uint32_t b[2]) {
    asm volatile("mma.sync.aligned.m16n8k16.row.col.f32.bf16.bf16.f32 "
                 "{%0,%1,%2,%3},{%4,%5,%6,%7},{%8,%9},{%0,%1,%2,%3};"
                 : "+f"(c[0]), "+f"(c[1]), "+f"(c[2]), "+f"(c[3])
                 : "r"(a[0]), "r"(a[1]), "r"(a[2]), "r"(a[3]), "r"(b[0]), "r"(b[1]));
}
DINLINE void cp16(uint32_t dst, const void* src) {
    asm volatile("cp.async.cg.shared.global [%0], [%1], 16;" :: "r"(dst), "l"(src) : "memory");
}
#define CP_COMMIT() asm volatile("cp.async.commit_group;" ::: "memory")
#define CP_WAIT1()  asm volatile("cp.async.wait_group 1;" ::: "memory")

// split fp32 pair into packed bf16 hi/lo
DINLINE void split2(float x, float y, uint32_t &hi, uint32_t &lo) {
    __nv_bfloat16 hx = __float2bfloat16(x);
    __nv_bfloat16 hy = __float2bfloat16(y);
    float rx = x - __bfloat162float(hx);
    float ry = y - __bfloat162float(hy);
    __nv_bfloat162 h2; h2.x = hx; h2.y = hy;
    __nv_bfloat162 l2; l2.x = __float2bfloat16(rx); l2.y = __float2bfloat16(ry);
    hi = *reinterpret_cast<uint32_t*>(&h2);
    lo = *reinterpret_cast<uint32_t*>(&l2);
}

// ===========================================================================
// Prep kernels
// ===========================================================================
__global__ __launch_bounds__(256) void split_x_kernel(const float* __restrict__ x) {
    int i = blockIdx.x * 256 + threadIdx.x;   // one float4
    float4 v = ((const float4*)x)[i];
    uint32_t h0, l0, h1, l1;
    split2(v.x, v.y, h0, l0);
    split2(v.z, v.w, h1, l1);
    ((uint2*)g_x_hi)[i] = make_uint2(h0, h1);
    ((uint2*)g_x_lo)[i] = make_uint2(l0, l1);
}

// src [K][N] fp32 -> plane set WSEL (0: w_qkv->g_wq, 1: w_proj->g_wp), [N][K] bf16 hi/lo
template <int WSEL>
__global__ __launch_bounds__(256) void tsplit_kernel(
    const float* __restrict__ src, int K, int N)
{
    __nv_bfloat16* dh = (WSEL == 0) ? g_wq_hi : g_wp_hi;
    __nv_bfloat16* dl = (WSEL == 0) ? g_wq_lo : g_wp_lo;
    __shared__ float T[32][33];
    int k0 = blockIdx.y * 32, n0 = blockIdx.x * 32;
    int tx = threadIdx.x & 31, ty = threadIdx.x >> 5;
#pragma unroll
    for (int i = 0; i < 4; i++)
        T[ty + 8 * i][tx] = src[(size_t)(k0 + ty + 8 * i) * N + n0 + tx];
    __syncthreads();
#pragma unroll
    for (int i = 0; i < 4; i++) {
        float v = T[tx][ty + 8 * i];
        __nv_bfloat16 h = __float2bfloat16(v);
        size_t o = (size_t)(n0 + ty + 8 * i) * K + k0 + tx;
        dh[o] = h;
        dl[o] = __float2bfloat16(v - __bfloat162float(h));
    }
}

// ===========================================================================
// bf16x3 mma.sync GEMM. Block 64x128, 4 warps, warp tile 64x32.
// BK=32, 2-stage cp.async pipeline, 3 CTAs/SM.
// ===========================================================================
#define PAe 40                        // smem pitch in bf16 elems (80B)
#define GA_PL (64*PAe)                // elems per A plane per stage (2560)
#define GB_PL (128*PAe)               // elems per B plane per stage (5120)
#define G_STG (2*GA_PL + 2*GB_PL)     // 15360 elems per stage
#define GEMM_SMEM_B (2 * G_STG * 2)   // 61440 bytes

template <bool QKV_EPI>
__global__ __launch_bounds__(128, 3) void mma_gemm_kernel(
    const float* __restrict__ bias, float* __restrict__ out)
{
    const __nv_bfloat16* Ah = QKV_EPI ? g_x_hi : g_o_hi;
    const __nv_bfloat16* Al = QKV_EPI ? g_x_lo : g_o_lo;
    const __nv_bfloat16* Bh = QKV_EPI ? g_wq_hi : g_wp_hi;
    const __nv_bfloat16* Bl = QKV_EPI ? g_wq_lo : g_wp_lo;

    extern __shared__ __nv_bfloat16 sm[];
    const int tid = threadIdx.x, lane = tid & 31, warp = tid >> 5;
    const int rowBase = blockIdx.y * 64, colBase = blockIdx.x * 128;

    float acc[4][4][4];
#pragma unroll
    for (int i = 0; i < 4; i++)
#pragma unroll
        for (int j = 0; j < 4; j++)
#pragma unroll
            for (int e = 0; e < 4; e++) acc[i][j][e] = 0.f;

    auto issue = [&](int st) {
        if (st < NKT) {
            const int k0 = st * 32;
            __nv_bfloat16* base = sm + (st & 1) * G_STG;
            // A: 64 rows x 32 cols -> 256 chunks/plane, 2 iters
#pragma unroll
            for (int i = 0; i < 2; i++) {
                int id = tid + i * 128;
                int r = id >> 2, c8 = (id & 3) * 8;
                uint32_t d = smem_u32(base + r * PAe + c8);
                size_t s = (size_t)(rowBase + r) * DIM + k0 + c8;
                cp16(d, Ah + s);
                cp16(d + GA_PL * 2, Al + s);
            }
            // B: 128 rows x 32 cols -> 512 chunks/plane, 4 iters
#pragma unroll
            for (int i = 0; i < 4; i++) {
                int id = tid + i * 128;
                int r = id >> 2, c8 = (id & 3) * 8;
                uint32_t d = smem_u32(base + 2 * GA_PL + r * PAe + c8);
                size_t s = (size_t)(colBase + r) * DIM + k0 + c8;
                cp16(d, Bh + s);
                cp16(d + GB_PL * 2, Bl + s);
            }
        }
        CP_COMMIT();
    };

    issue(0);
    issue(1);

    const int a_ro = (lane & 7) + 8 * ((lane >> 3) & 1);
    const int a_co = 8 * (lane >> 4);
    const int b_ro = (lane & 7) + 8 * (lane >> 4);
    const int b_co = 8 * ((lane >> 3) & 1);

    for (int t = 0; t < NKT; t++) {
        CP_WAIT1();
        __syncthreads();
        const __nv_bfloat16* stg = sm + (t & 1) * G_STG;
        const __nv_bfloat16* sAh = stg;
        const __nv_bfloat16* sAl = stg + GA_PL;
        const __nv_bfloat16* sBh = stg + 2 * GA_PL;
        const __nv_bfloat16* sBl = stg + 2 * GA_PL + GB_PL;

#pragma unroll
        for (int ks = 0; ks < 2; ks++) {
            uint32_t afh[4][4], afl[4][4];
#pragma unroll
            for (int ma = 0; ma < 4; ma++) {
                int off = (ma * 16 + a_ro) * PAe + ks * 16 + a_co;
                ldsm4(afh[ma], smem_u32(sAh + off));
                ldsm4(afl[ma], smem_u32(sAl + off));
            }
#pragma unroll
            for (int nb = 0; nb < 2; nb++) {
                int off = (warp * 32 + nb * 16 + b_ro) * PAe + ks * 16 + b_co;
                uint32_t bfh[4], bfl[4];
                ldsm4(bfh, smem_u32(sBh + off));
                ldsm4(bfl, smem_u32(sBl + off));
#pragma unroll
                for (int ma = 0; ma < 4; ma++) {
                    mma16816(acc[ma][2*nb],   afh[ma], &bfh[0]);
                    mma16816(acc[ma][2*nb+1], afh[ma], &bfh[2]);
                    mma16816(acc[ma][2*nb],   afh[ma], &bfl[0]);
                    mma16816(acc[ma][2*nb+1], afh[ma], &bfl[2]);
                    mma16816(acc[ma][2*nb],   afl[ma], &bfh[0]);
                    mma16816(acc[ma][2*nb+1], afl[ma], &bfh[2]);
                }
            }
        }
        __syncthreads();
        issue(t + 2);
    }

    // ---------------- epilogue ----------------
    const int g = lane >> 2, tq = lane & 3;
#pragma unroll
    for (int ma = 0; ma < 4; ma++) {
#pragma unroll
        for (int half = 0; half < 2; half++) {
            int row = rowBase + ma * 16 + g + half * 8;
            if (QKV_EPI) {
                int b = row >> 10, srow = row & 1023;
#pragma unroll
                for (int nn = 0; nn < 4; nn++) {
                    int col = colBase + warp * 32 + nn * 8 + 2 * tq;
                    float v0 = acc[ma][nn][half * 2 + 0] + bias[col];
                    float v1 = acc[ma][nn][half * 2 + 1] + bias[col + 1];
                    int which = col / DIM;
                    int rem = col - which * DIM;
                    int h = rem >> 6, d = rem & 63;
                    size_t idx = (((size_t)(b * HEADS + h)) * SEQ + srow) * HDIM + d;
                    __nv_bfloat16* dh = (which == 0) ? g_q_hi : (which == 1) ? g_k_hi : g_v_hi;
                    __nv_bfloat16* dl = (which == 0) ? g_q_lo : (which == 1) ? g_k_lo : g_v_lo;
                    uint32_t hi, lo;
                    split2(v0, v1, hi, lo);
                    *(uint32_t*)(dh + idx) = hi;
                    *(uint32_t*)(dl + idx) = lo;
                }
            } else {
#pragma unroll
                for (int nn = 0; nn < 4; nn++) {
                    int col = colBase + warp * 32 + nn * 8 + 2 * tq;
                    float2 o;
                    o.x = acc[ma][nn][half * 2 + 0] + bias[col];
                    o.y = acc[ma][nn][half * 2 + 1] + bias[col + 1];
                    *(float2*)(out + (size_t)row * DIM + col) = o;
                }
            }
        }
    }
}

// ===========================================================================
// Flash attention: Br=64, 4 warps (128 thr), 2 CTAs/SM, cp.async 2-stage KV.
// Warp owns 16 q-rows; softmax structure identical to the passing version.
// ===========================================================================
#define QPITCH 72
#define Q_PL (64*QPITCH)                  // elems per Q plane (4608)
#define KV_STG (4*Q_PL)                   // elems per KV stage (4 planes)
#define AT_SMEM_BYTES ((2*Q_PL + 2*KV_STG) * 2)   // 92160 bytes

__global__ __launch_bounds__(128, 2) void attn_kernel()
{
    extern __shared__ __nv_bfloat16 smb[];
    const int tid = threadIdx.x, lane = tid & 31, warp = tid >> 5;
    const int bh = blockIdx.y, qt = blockIdx.x;
    const int g = lane >> 2, t = lane & 3;
    const float scale = 0.125f;

    const size_t base = (size_t)bh * SEQ * HDIM;
    const __nv_bfloat16* qh = g_q_hi + base; const __nv_bfloat16* ql = g_q_lo + base;
    const __nv_bfloat16* kh = g_k_hi + base; const __nv_bfloat16* kl = g_k_lo + base;
    const __nv_bfloat16* vh = g_v_hi + base; const __nv_bfloat16* vl = g_v_lo + base;

    __nv_bfloat16* Qs_hi = smb;
    __nv_bfloat16* Qs_lo = smb + Q_PL;

    // Q tile (64x64) both planes via cp.async (part of group 0)
#pragma unroll
    for (int i = 0; i < 4; i++) {
        int id = tid + i * 128;
        int r = id >> 3, c8 = (id & 7) * 8;
        size_t s = (size_t)(qt * 64 + r) * HDIM + c8;
        cp16(smem_u32(Qs_hi + r * QPITCH + c8), qh + s);
        cp16(smem_u32(Qs_lo + r * QPITCH + c8), ql + s);
    }

    auto issue_kv = [&](int kt) {
        if (kt < SEQ / 64) {
            __nv_bfloat16* sb = smb + 2 * Q_PL + (kt & 1) * KV_STG;
#pragma unroll
            for (int i = 0; i < 4; i++) {
                int id = tid + i * 128;
                int r = id >> 3, c8 = (id & 7) * 8;
                int doff = r * QPITCH + c8;
                size_t s = (size_t)(kt * 64 + r) * HDIM + c8;
                cp16(smem_u32(sb + doff),            kh + s);
                cp16(smem_u32(sb + Q_PL + doff),     kl + s);
                cp16(smem_u32(sb + 2 * Q_PL + doff), vh + s);
                cp16(smem_u32(sb + 3 * Q_PL + doff), vl + s);
            }
        }
        CP_COMMIT();
    };

    issue_kv(0);   // commits Q copies + KV tile 0
    issue_kv(1);

    CP_WAIT1();
    __syncthreads();

    // Q fragments resident in regs (warp's 16 rows)
    const int a_row = warp * 16 + (lane & 7) + 8 * ((lane >> 3) & 1);
    const int a_col = 8 * (lane >> 4);
    uint32_t qfh[4][4], qfl[4][4];
#pragma unroll
    for (int ka = 0; ka < 4; ka++) {
        int off = a_row * QPITCH + ka * 16 + a_col;
        ldsm4(qfh[ka], smem_u32(&Qs_hi[off]));
        ldsm4(qfl[ka], smem_u32(&Qs_lo[off]));
    }

    const int k_row = (lane & 7) + 8 * (lane >> 4);
    const int k_col = 8 * ((lane >> 3) & 1);
    const int v_row = (lane & 7) + 8 * ((lane >> 3) & 1);
    const int v_col = 8 * (lane >> 4);

    float m0 = -1e30f, m1 = -1e30f, l0 = 0.f, l1 = 0.f;
    float o[8][4];
#pragma unroll
    for (int j = 0; j < 8; j++)
#pragma unroll
        for (int e = 0; e < 4; e++) o[j][e] = 0.f;

    for (int kt = 0; kt < SEQ / 64; kt++) {
        const __nv_bfloat16* sb = smb + 2 * Q_PL + (kt & 1) * KV_STG;
        const __nv_bfloat16* Ksh = sb;
        const __nv_bfloat16* Ksl = sb + Q_PL;
        const __nv_bfloat16* Vsh = sb + 2 * Q_PL;
        const __nv_bfloat16* Vsl = sb + 3 * Q_PL;

        // ---- S = Q K^T (bf16x3) ----
        float s[8][4];
#pragma unroll
        for (int j = 0; j < 8; j++)
#pragma unroll
            for (int e = 0; e < 4; e++) s[j][e] = 0.f;

#pragma unroll
        for (int nb = 0; nb < 4; nb++) {
#pragma unroll
            for (int ka = 0; ka < 4; ka++) {
                int off = (nb * 16 + k_row) * QPITCH + ka * 16 + k_col;
                uint32_t kfh[4], kfl[4];
                ldsm4(kfh, smem_u32(Ksh + off));
                ldsm4(kfl, smem_u32(Ksl + off));
                mma16816(s[2*nb],   qfh[ka], &kfh[0]);
                mma16816(s[2*nb+1], qfh[ka], &kfh[2]);
                mma16816(s[2*nb],   qfh[ka], &kfl[0]);
                mma16816(s[2*nb+1], qfh[ka], &kfl[2]);
                mma16816(s[2*nb],   qfl[ka], &kfh[0]);
                mma16816(s[2*nb+1], qfl[ka], &kfh[2]);
            }
        }

        // ---- online softmax ----
        float mx0 = -1e30f, mx1 = -1e30f;
#pragma unroll
        for (int j = 0; j < 8; j++) {
            s[j][0] *= scale; s[j][1] *= scale; s[j][2] *= scale; s[j][3] *= scale;
            mx0 = fmaxf(mx0, fmaxf(s[j][0], s[j][1]));
            mx1 = fmaxf(mx1, fmaxf(s[j][2], s[j][3]));
        }
        mx0 = fmaxf(mx0, __shfl_xor_sync(0xffffffffu, mx0, 1));
        mx0 = fmaxf(mx0, __shfl_xor_sync(0xffffffffu, mx0, 2));
        mx1 = fmaxf(mx1, __shfl_xor_sync(0xffffffffu, mx1, 1));
        mx1 = fmaxf(mx1, __shfl_xor_sync(0xffffffffu, mx1, 2));
        float mn0 = fmaxf(m0, mx0), mn1 = fmaxf(m1, mx1);
        float c0 = __expf(m0 - mn0), c1 = __expf(m1 - mn1);
        float p[8][4];
        float ls0 = 0.f, ls1 = 0.f;
#pragma unroll
        for (int j = 0; j < 8; j++) {
            p[j][0] = __expf(s[j][0] - mn0); p[j][1] = __expf(s[j][1] - mn0);
            p[j][2] = __expf(s[j][2] - mn1); p[j][3] = __expf(s[j][3] - mn1);
            ls0 += p[j][0] + p[j][1];
            ls1 += p[j][2] + p[j][3];
        }
        ls0 += __shfl_xor_sync(0xffffffffu, ls0, 1);
        ls0 += __shfl_xor_sync(0xffffffffu, ls0, 2);
        ls1 += __shfl_xor_sync(0xffffffffu, ls1, 1);
        ls1 += __shfl_xor_sync(0xffffffffu, ls1, 2);
        l0 = l0 * c0 + ls0; m0 = mn0;
        l1 = l1 * c1 + ls1; m1 = mn1;
#pragma unroll
        for (int j = 0; j < 8; j++) {
            o[j][0] *= c0; o[j][1] *= c0; o[j][2] *= c1; o[j][3] *= c1;
        }

        // ---- P fragments ----
        uint32_t pfh[4][4], pfl[4][4];
#pragma unroll
        for (int ka = 0; ka < 4; ka++) {
            split2(p[2*ka][0],   p[2*ka][1],   pfh[ka][0], pfl[ka][0]);
            split2(p[2*ka][2],   p[2*ka][3],   pfh[ka][1], pfl[ka][1]);
            split2(p[2*ka+1][0], p[2*ka+1][1], pfh[ka][2], pfl[ka][2]);
            split2(p[2*ka+1][2], p[2*ka+1][3], pfh[ka][3], pfl[ka][3]);
        }

        // ---- O += P V (bf16x3) ----
#pragma unroll
        for (int nb = 0; nb < 4; nb++) {
#pragma unroll
            for (int ka = 0; ka < 4; ka++) {
                int off = (ka * 16 + v_row) * QPITCH + nb * 16 + v_col;
                uint32_t vfh[4], vfl[4];
                ldsm4t(vfh, smem_u32(Vsh + off));
                ldsm4t(vfl, smem_u32(Vsl + off));
                mma16816(o[2*nb],   pfh[ka], &vfh[0]);
                mma16816(o[2*nb+1], pfh[ka], &vfh[2]);
                mma16816(o[2*nb],   pfh[ka], &vfl[0]);
                mma16816(o[2*nb+1], pfh[ka], &vfl[2]);
                mma16816(o[2*nb],   pfl[ka], &vfh[0]);
                mma16816(o[2*nb+1], pfl[ka], &vfh[2]);
            }
        }

        // pipeline: protect buffer overwrite, refill, wait next stage
        __syncthreads();
        issue_kv(kt + 2);
        CP_WAIT1();
        __syncthreads();
    }

    // ---- normalize + write O as hi/lo bf16 into [B,S,D] planes ----
    float i0 = 1.f / l0, i1 = 1.f / l1;
    int b = bh / HEADS, h = bh - (bh / HEADS) * HEADS;
    int srow0 = qt * 64 + warp * 16 + g;
    int srow1 = srow0 + 8;
#pragma unroll
    for (int j = 0; j < 8; j++) {
        int col = h * HDIM + j * 8 + 2 * t;
        size_t i0x = ((size_t)(b * SEQ) + srow0) * DIM + col;
        size_t i1x = ((size_t)(b * SEQ) + srow1) * DIM + col;
        uint32_t hi, lo;
        split2(o[j][0] * i0, o[j][1] * i0, hi, lo);
        *(uint32_t*)(g_o_hi + i0x) = hi;
        *(uint32_t*)(g_o_lo + i0x) = lo;
        split2(o[j][2] * i1, o[j][3] * i1, hi, lo);
        *(uint32_t*)(g_o_hi + i1x) = hi;
        *(uint32_t*)(g_o_lo + i1x) = lo;
    }
}

// ===========================================================================
extern "C" void kernel_launch(void* const* d_in, const int* in_sizes, int n_in,
                              void* d_out, int out_size) {
    const float* x      = (const float*)d_in[0];
    const float* w_qkv  = (const float*)d_in[1];
    const float* b_qkv  = (const float*)d_in[2];
    const float* w_proj = (const float*)d_in[3];
    const float* b_proj = (const float*)d_in[4];
    float* out = (float*)d_out;

    cudaFuncSetAttribute(attn_kernel, cudaFuncAttributeMaxDynamicSharedMemorySize,
                         AT_SMEM_BYTES);
    cudaFuncSetAttribute(mma_gemm_kernel<true>, cudaFuncAttributeMaxDynamicSharedMemorySize,
                         GEMM_SMEM_B);
    cudaFuncSetAttribute(mma_gemm_kernel<false>, cudaFuncAttributeMaxDynamicSharedMemorySize,
                         GEMM_SMEM_B);

    // prep: split x, transpose+split weights (destinations resolved in device code)
    split_x_kernel<<<M_ROWS * DIM / 1024, 256>>>(x);
    tsplit_kernel<0><<<dim3(N_QKV / 32, DIM / 32), 256>>>(w_qkv, DIM, N_QKV);
    tsplit_kernel<1><<<dim3(DIM / 32, DIM / 32), 256>>>(w_proj, DIM, DIM);

    // QKV GEMM: M=8192, N=2304
    mma_gemm_kernel<true><<<dim3(N_QKV / 128, M_ROWS / 64), 128, GEMM_SMEM_B>>>(
        b_qkv, nullptr);

    // attention: 16 q-tiles x 96 bh
    attn_kernel<<<dim3(SEQ / 64, BATCH * HEADS), 128, AT_SMEM_BYTES>>>();

    // proj GEMM: M=8192, N=768
    mma_gemm_kernel<false><<<dim3(DIM / 128, M_ROWS / 64), 128, GEMM_SMEM_B>>>(
        b_proj, out);
}